// round 3
// baseline (speedup 1.0000x reference)
#include <cuda_runtime.h>
#include <cuda_fp16.h>
#include <mma.h>
#include <cstdint>

using namespace nvcuda;

// Problem constants
#define Bb 8
#define Cc 64
#define Nn 500
#define Tt 12
#define Hh 4
#define Ff 64
#define Ss (Bb * Tt)   // 96 slices (b,t)
#define HF (Hh * Ff)   // 256
#define MAXD 128
#define ALPHAc 0.05f
#define LEAKc 0.2f

// ---------------- scratch (device globals; no allocation) ----------------
__device__ float   g_xT[Ss * Nn * Cc];                 // [s,n,c]
__device__ float   g_h1T[Ss * Nn * Cc];
__device__ float   g_h2T[Ss * Nn * Cc];
__device__ __half2 g_Wh16[(size_t)Ss * Nn * (HF / 2)]; // [s,n,hf/2] fp16 pairs
__device__ float   g_hpr[(size_t)Ss * Nn * HF];        // [s,n,h*F+f] fp32
__device__ float   g_e1[Ss * Hh * Nn];                 // [(s*H+h)*N + n]
__device__ float   g_e2[Ss * Hh * Nn];
__device__ float   g_Wcat[Cc * HF];                    // [c, h*F+f]
__device__ float   g_WgT[HF * Cc];                     // [hf, o]
__device__ float   g_WmT[3 * Cc * Cc];                 // [c_global, o]
__device__ int     g_cnt[Nn];
__device__ int     g_nbr[Nn * MAXD];

// ---------------- neighbor list (deterministic warp scan, warp per row) ----------------
__global__ void build_nbr(const float* __restrict__ adj) {
    int warp = threadIdx.x >> 5;
    int lane = threadIdx.x & 31;
    int n = blockIdx.x * 4 + warp;
    if (n >= Nn) return;
    int base = 0;
    for (int m0 = 0; m0 < 512; m0 += 32) {
        int m = m0 + lane;
        bool p = (m < Nn) && (adj[n * Nn + m] > 0.f || m == n);
        unsigned mask = __ballot_sync(0xffffffffu, p);
        if (p) {
            int r = __popc(mask & ((1u << lane) - 1));
            if (base + r < MAXD) g_nbr[n * MAXD + base + r] = m;
        }
        base += __popc(mask);
    }
    if (lane == 0) g_cnt[n] = base < MAXD ? base : MAXD;
}

// ---------------- weight re-layouts ----------------
__global__ void prep_weights(const float* __restrict__ W,
                             const float* __restrict__ Wg,
                             const float* __restrict__ Wm) {
    int i = blockIdx.x * blockDim.x + threadIdx.x;
    if (i < Hh * Cc * Ff) {  // Wcat[c, h*F+f] = W[h,c,f]
        int f = i % Ff; int rest = i / Ff;
        int c = rest % Cc; int h = rest / Cc;
        g_Wcat[c * HF + h * Ff + f] = W[(h * Cc + c) * Ff + f];
    }
    if (i < HF * Cc) {       // WgT[hf, o] = Wg[o, hf]
        int o = i % Cc; int hf = i / Cc;
        g_WgT[hf * Cc + o] = Wg[o * HF + hf];
    }
    if (i < 3 * Cc * Cc) {   // WmT[c, o] = Wm[o, c]
        int o = i % Cc; int c = i / Cc;
        g_WmT[c * Cc + o] = Wm[o * (3 * Cc) + c];
    }
}

// ---------------- tiled input transpose: x[b,c,n,t] -> xT[s,n,c] ----------------
__global__ void transpose_in(const float* __restrict__ x, float* __restrict__ xT) {
    __shared__ float sm[16][193];
    const int b = blockIdx.z, c0 = blockIdx.y * 16, n0 = blockIdx.x * 16;
    const int tt_ = threadIdx.x;            // 0..191
    const int ni_l = tt_ / 12, tl = tt_ % 12;
    const int n_l = n0 + ni_l;
    #pragma unroll
    for (int ci = 0; ci < 16; ++ci) {
        float v = 0.f;
        if (n_l < Nn)
            v = x[(((size_t)b * Cc + c0 + ci) * Nn + n_l) * Tt + tl];
        sm[ci][tt_] = v;
    }
    __syncthreads();
    #pragma unroll
    for (int rep = 0; rep < 16; ++rep) {
        int idx = rep * 192 + tt_;          // 0..3071
        int ci = idx & 15;
        int rest = idx >> 4;                // ni*12 + t
        int ni = rest / 12, t = rest % 12;
        int n = n0 + ni;
        if (n < Nn)
            xT[(((size_t)(b * Tt + t) * Nn) + n) * Cc + c0 + ci] = sm[ci][rest];
    }
}

// ================= tf32 wmma projection GEMM + fused e1/e2 + fp16 Wh =================
// grid (Ss, 8, Hh), block 256 (8 warps). Tile 64x64, K=64.
__global__ void gemm_proj_tc(const float* __restrict__ A,
                             const float* __restrict__ a1,
                             const float* __restrict__ a2) {
    __shared__ __align__(32) float As[64][72];
    __shared__ __align__(32) float Bs[64][72];
    const int s = blockIdx.x;
    const int r0 = blockIdx.y * 64;
    const int h = blockIdx.z;
    const int c0 = h * 64;
    const float* Asl = A + (size_t)s * Nn * Cc;
    const int tid = threadIdx.x;
    const int wid = tid >> 5;
    const int wm = wid & 3, wn = wid >> 2;   // warp tile: rows wm*16, cols wn*32

    #pragma unroll 4
    for (int i = tid; i < 64 * 64; i += 256) {
        int r = i >> 6, k = i & 63;
        int row = r0 + r;
        As[r][k] = (row < Nn) ? Asl[(size_t)row * Cc + k] : 0.f;
    }
    #pragma unroll 4
    for (int i = tid; i < 64 * 64; i += 256) {
        int k = i >> 6, c = i & 63;
        Bs[k][c] = g_Wcat[k * HF + c0 + c];
    }
    __syncthreads();

    wmma::fragment<wmma::accumulator, 16, 16, 8, float> fc[2];
    wmma::fill_fragment(fc[0], 0.f);
    wmma::fill_fragment(fc[1], 0.f);
    #pragma unroll
    for (int k0 = 0; k0 < 64; k0 += 8) {
        wmma::fragment<wmma::matrix_a, 16, 16, 8, wmma::precision::tf32, wmma::row_major> fa;
        wmma::load_matrix_sync(fa, &As[wm * 16][k0], 72);
        #pragma unroll
        for (int i = 0; i < fa.num_elements; ++i) fa.x[i] = wmma::__float_to_tf32(fa.x[i]);
        #pragma unroll
        for (int sub = 0; sub < 2; ++sub) {
            wmma::fragment<wmma::matrix_b, 16, 16, 8, wmma::precision::tf32, wmma::row_major> fb;
            wmma::load_matrix_sync(fb, &Bs[k0][wn * 32 + sub * 16], 72);
            #pragma unroll
            for (int i = 0; i < fb.num_elements; ++i) fb.x[i] = wmma::__float_to_tf32(fb.x[i]);
            wmma::mma_sync(fc[sub], fa, fb, fc[sub]);
        }
    }
    __syncthreads();   // done reading As/Bs
    wmma::store_matrix_sync(&As[wm * 16][wn * 32], fc[0], 72, wmma::mem_row_major);
    wmma::store_matrix_sync(&As[wm * 16][wn * 32 + 16], fc[1], 72, wmma::mem_row_major);
    __syncthreads();

    // fused e1/e2: thread t -> row t>>2, quarter t&3 (16 cols each); reduce over 4 lanes
    {
        const int row = tid >> 2, q = tid & 3;
        float s1 = 0.f, s2 = 0.f;
        #pragma unroll
        for (int i = 0; i < 16; ++i) {
            int c = q * 16 + i;
            float v = As[row][c];
            s1 = fmaf(v, a1[c0 + c], s1);
            s2 = fmaf(v, a2[c0 + c], s2);
        }
        s1 += __shfl_xor_sync(0xffffffffu, s1, 1);
        s2 += __shfl_xor_sync(0xffffffffu, s2, 1);
        s1 += __shfl_xor_sync(0xffffffffu, s1, 2);
        s2 += __shfl_xor_sync(0xffffffffu, s2, 2);
        if (q == 0 && r0 + row < Nn) {
            const int sh = s * Hh + h;
            g_e1[sh * Nn + r0 + row] = s1;
            g_e2[sh * Nn + r0 + row] = s2;
        }
    }

    // fp16 Wh store (coalesced): 64 rows x 32 half2
    #pragma unroll
    for (int k = 0; k < 8; ++k) {
        int idx = k * 256 + tid;
        int r = idx >> 5, p = idx & 31;
        if (r0 + r < Nn) {
            g_Wh16[((size_t)s * Nn + r0 + r) * (HF / 2) + (c0 >> 1) + p] =
                __floats2half2_rn(As[r][2 * p], As[r][2 * p + 1]);
        }
    }
}

// ================= tf32 wmma mix GEMM: h_next = a*x + (1-a)*(hpr @ WgT + bg) =========
// grid (Ss, 8), block 256. Tile 64x64, K=256.
__global__ void gemm_mix_tc(const float* __restrict__ Ain,
                            const float* __restrict__ bias,
                            const float* __restrict__ resid,
                            float* __restrict__ Cm) {
    __shared__ __align__(32) float As[64][72];
    __shared__ __align__(32) float Bs[64][72];
    const int s = blockIdx.x;
    const int r0 = blockIdx.y * 64;
    const float* Asl = Ain + (size_t)s * Nn * HF;
    const int tid = threadIdx.x;
    const int wid = tid >> 5;
    const int wm = wid & 3, wn = wid >> 2;

    wmma::fragment<wmma::accumulator, 16, 16, 8, float> fc[2];
    wmma::fill_fragment(fc[0], 0.f);
    wmma::fill_fragment(fc[1], 0.f);

    for (int kb = 0; kb < HF; kb += 64) {
        #pragma unroll 4
        for (int i = tid; i < 64 * 64; i += 256) {
            int r = i >> 6, k = i & 63;
            int row = r0 + r;
            As[r][k] = (row < Nn) ? Asl[(size_t)row * HF + kb + k] : 0.f;
        }
        #pragma unroll 4
        for (int i = tid; i < 64 * 64; i += 256) {
            int k = i >> 6, c = i & 63;
            Bs[k][c] = g_WgT[(kb + k) * Cc + c];
        }
        __syncthreads();
        #pragma unroll
        for (int k0 = 0; k0 < 64; k0 += 8) {
            wmma::fragment<wmma::matrix_a, 16, 16, 8, wmma::precision::tf32, wmma::row_major> fa;
            wmma::load_matrix_sync(fa, &As[wm * 16][k0], 72);
            #pragma unroll
            for (int i = 0; i < fa.num_elements; ++i) fa.x[i] = wmma::__float_to_tf32(fa.x[i]);
            #pragma unroll
            for (int sub = 0; sub < 2; ++sub) {
                wmma::fragment<wmma::matrix_b, 16, 16, 8, wmma::precision::tf32, wmma::row_major> fb;
                wmma::load_matrix_sync(fb, &Bs[k0][wn * 32 + sub * 16], 72);
                #pragma unroll
                for (int i = 0; i < fb.num_elements; ++i) fb.x[i] = wmma::__float_to_tf32(fb.x[i]);
                wmma::mma_sync(fc[sub], fa, fb, fc[sub]);
            }
        }
        __syncthreads();
    }
    wmma::store_matrix_sync(&As[wm * 16][wn * 32], fc[0], 72, wmma::mem_row_major);
    wmma::store_matrix_sync(&As[wm * 16][wn * 32 + 16], fc[1], 72, wmma::mem_row_major);
    __syncthreads();

    #pragma unroll
    for (int k = 0; k < 16; ++k) {
        int idx = k * 256 + tid;
        int r = idx >> 6, c = idx & 63;
        int row = r0 + r;
        if (row < Nn) {
            size_t oidx = ((size_t)s * Nn + row) * Cc + c;
            Cm[oidx] = ALPHAc * resid[oidx] + (1.f - ALPHAc) * (As[r][c] + bias[c]);
        }
    }
}

// ---------------- attention softmax + aggregation: block per (n,s), 128 thr ----------------
__global__ void attn_agg(float* __restrict__ hpr) {
    const int n = blockIdx.x, s = blockIdx.y;
    const int t = threadIdx.x;        // 0..127 -> hf pair 2t,2t+1
    const int h = t >> 5, lane = t & 31;
    __shared__ int snbr[MAXD];
    __shared__ float sw[Hh][MAXD];

    const int cnt = min(g_cnt[n], MAXD);
    for (int j = t; j < cnt; j += 128) snbr[j] = g_nbr[n * MAXD + j];
    __syncthreads();

    const int sh = s * Hh + h;
    const float e1v = g_e1[sh * Nn + n];
    const float* e2r = g_e2 + (size_t)sh * Nn;
    float ev[4];
    float mx = -1e30f;
    #pragma unroll
    for (int k = 0; k < 4; ++k) {
        int j = k * 32 + lane;
        float e = -1e30f;
        if (j < cnt) {
            float tv = e1v + e2r[snbr[j]];
            e = tv > 0.f ? tv : LEAKc * tv;
        }
        ev[k] = e;
        mx = fmaxf(mx, e);
    }
    #pragma unroll
    for (int o = 16; o; o >>= 1) mx = fmaxf(mx, __shfl_xor_sync(0xffffffffu, mx, o));
    float sum = 0.f;
    #pragma unroll
    for (int k = 0; k < 4; ++k) {
        float w = (k * 32 + lane < cnt) ? __expf(ev[k] - mx) : 0.f;
        ev[k] = w;
        sum += w;
    }
    #pragma unroll
    for (int o = 16; o; o >>= 1) sum += __shfl_xor_sync(0xffffffffu, sum, o);
    const float inv = 1.f / sum;
    #pragma unroll
    for (int k = 0; k < 4; ++k) {
        int j = k * 32 + lane;
        if (j < cnt) sw[h][j] = ev[k] * inv;
    }
    __syncthreads();

    const size_t rowB = (size_t)s * Nn;
    const float* swh = sw[h];
    float ax = 0.f, ay = 0.f;
    int j = 0;
    for (; j + 4 <= cnt; j += 4) {
        int m0 = snbr[j], m1 = snbr[j + 1], m2 = snbr[j + 2], m3 = snbr[j + 3];
        float w0 = swh[j], w1 = swh[j + 1], w2 = swh[j + 2], w3 = swh[j + 3];
        float2 f0 = __half22float2(g_Wh16[(rowB + m0) * (HF / 2) + t]);
        float2 f1 = __half22float2(g_Wh16[(rowB + m1) * (HF / 2) + t]);
        float2 f2 = __half22float2(g_Wh16[(rowB + m2) * (HF / 2) + t]);
        float2 f3 = __half22float2(g_Wh16[(rowB + m3) * (HF / 2) + t]);
        ax = fmaf(w0, f0.x, fmaf(w1, f1.x, fmaf(w2, f2.x, fmaf(w3, f3.x, ax))));
        ay = fmaf(w0, f0.y, fmaf(w1, f1.y, fmaf(w2, f2.y, fmaf(w3, f3.y, ay))));
    }
    for (; j < cnt; ++j) {
        float w = swh[j];
        float2 f = __half22float2(g_Wh16[(rowB + snbr[j]) * (HF / 2) + t]);
        ax = fmaf(w, f.x, ax);
        ay = fmaf(w, f.y, ay);
    }
    float2 o2;
    o2.x = ax > 0.f ? ax : (__expf(ax) - 1.f);
    o2.y = ay > 0.f ? ay : (__expf(ay) - 1.f);
    ((float2*)hpr)[(rowB + n) * (HF / 2) + t] = o2;
}

// ---------------- final: out[b,o,n,t] = bm[o] + Wm @ [x; h1; h2] (exact fp32) ----------
__global__ void final_out(const float* __restrict__ xT,
                          const float* __restrict__ h1,
                          const float* __restrict__ h2,
                          const float* __restrict__ bm,
                          float* __restrict__ out) {
    __shared__ float sX[16][64], sH1[16][64], sH2[16][64];
    const int s = blockIdx.x;
    const int n0 = blockIdx.y * 16;
    const int tid = threadIdx.x;
    for (int i = tid; i < 16 * 64; i += 256) {
        int nl = i >> 6, c = i & 63;
        int n = n0 + nl;
        size_t idx = ((size_t)s * Nn + (n < Nn ? n : 0)) * Cc + c;
        sX[nl][c]  = (n < Nn) ? xT[idx] : 0.f;
        sH1[nl][c] = (n < Nn) ? h1[idx] : 0.f;
        sH2[nl][c] = (n < Nn) ? h2[idx] : 0.f;
    }
    __syncthreads();
    const int o = tid & 63, ng = tid >> 6;
    float acc[4] = {0.f, 0.f, 0.f, 0.f};
    #pragma unroll 4
    for (int c = 0; c < 64; ++c) {
        float w0 = g_WmT[c * Cc + o];
        float w1 = g_WmT[(64 + c) * Cc + o];
        float w2 = g_WmT[(128 + c) * Cc + o];
        #pragma unroll
        for (int r = 0; r < 4; ++r) {
            int nl = ng + r * 4;
            acc[r] = fmaf(w0, sX[nl][c], fmaf(w1, sH1[nl][c], fmaf(w2, sH2[nl][c], acc[r])));
        }
    }
    const int b = s / Tt, t = s % Tt;
    const float bias = bm[o];
    #pragma unroll
    for (int r = 0; r < 4; ++r) {
        int n = n0 + ng + r * 4;
        if (n < Nn)
            out[(((size_t)b * Cc + o) * Nn + n) * Tt + t] = acc[r] + bias;
    }
}

// ---------------- launch ----------------
extern "C" void kernel_launch(void* const* d_in, const int* in_sizes, int n_in,
                              void* d_out, int out_size) {
    const float* x   = (const float*)d_in[0];
    const float* adj = (const float*)d_in[1];
    const float* W   = (const float*)d_in[2];
    const float* a1  = (const float*)d_in[3];
    const float* a2  = (const float*)d_in[4];
    const float* Wg  = (const float*)d_in[5];
    const float* bg  = (const float*)d_in[6];
    const float* Wm  = (const float*)d_in[7];
    const float* bm  = (const float*)d_in[8];
    float* out = (float*)d_out;

    float *xT, *h1T, *h2T, *hpr;
    cudaGetSymbolAddress((void**)&xT,  g_xT);
    cudaGetSymbolAddress((void**)&h1T, g_h1T);
    cudaGetSymbolAddress((void**)&h2T, g_h2T);
    cudaGetSymbolAddress((void**)&hpr, g_hpr);

    build_nbr<<<125, 128>>>(adj);
    prep_weights<<<64, 256>>>(W, Wg, Wm);
    transpose_in<<<dim3(32, 4, Bb), 192>>>(x, xT);

    const float* hin = xT;
    float* hb[2] = {h1T, h2T};
    for (int it = 0; it < 2; ++it) {
        gemm_proj_tc<<<dim3(Ss, 8, Hh), 256>>>(hin, a1, a2);
        attn_agg<<<dim3(Nn, Ss), 128>>>(hpr);
        gemm_mix_tc<<<dim3(Ss, 8), 256>>>(hpr, bg, xT, hb[it]);
        hin = hb[it];
    }
    final_out<<<dim3(Ss, (Nn + 15) / 16), 256>>>(xT, h1T, h2T, bm, out);
}

// round 4
// speedup vs baseline: 1.0050x; 1.0050x over previous
#include <cuda_runtime.h>
#include <cuda_fp16.h>
#include <mma.h>
#include <cstdint>

using namespace nvcuda;

// Problem constants
#define Bb 8
#define Cc 64
#define Nn 500
#define Tt 12
#define Hh 4
#define Ff 64
#define Ss (Bb * Tt)   // 96 slices (b,t)
#define HF (Hh * Ff)   // 256
#define MAXD 128
#define ALPHAc 0.05f
#define LEAKc 0.2f

// ---------------- scratch (device globals; no allocation) ----------------
__device__ float   g_xT[Ss * Nn * Cc];                 // [s,n,c]
__device__ float   g_h1T[Ss * Nn * Cc];
__device__ float   g_h2T[Ss * Nn * Cc];
__device__ __half2 g_Wh16[(size_t)Ss * Nn * (HF / 2)]; // [s,n,hf/2] fp16 pairs
__device__ float   g_hpr[(size_t)Ss * Nn * HF];        // [s,n,h*F+f] fp32
__device__ float   g_e1[Ss * Hh * Nn];                 // [(s*H+h)*N + n]
__device__ float   g_e2[Ss * Hh * Nn];
__device__ float   g_Wcat[Cc * HF];                    // [c, h*F+f]
__device__ float   g_WgT[HF * Cc];                     // [hf, o]
__device__ float   g_WmT[3 * Cc * Cc];                 // [c_global, o]
__device__ int     g_cnt[Nn];
__device__ int     g_nbr[Nn * MAXD];

// ---------------- neighbor list (deterministic warp scan, warp per row) ----------------
__global__ void build_nbr(const float* __restrict__ adj) {
    int warp = threadIdx.x >> 5;
    int lane = threadIdx.x & 31;
    int n = blockIdx.x * 4 + warp;
    if (n >= Nn) return;
    int base = 0;
    for (int m0 = 0; m0 < 512; m0 += 32) {
        int m = m0 + lane;
        bool p = (m < Nn) && (adj[n * Nn + m] > 0.f || m == n);
        unsigned mask = __ballot_sync(0xffffffffu, p);
        if (p) {
            int r = __popc(mask & ((1u << lane) - 1));
            if (base + r < MAXD) g_nbr[n * MAXD + base + r] = m;
        }
        base += __popc(mask);
    }
    if (lane == 0) g_cnt[n] = base < MAXD ? base : MAXD;
}

// ---------------- weight re-layouts ----------------
__global__ void prep_weights(const float* __restrict__ W,
                             const float* __restrict__ Wg,
                             const float* __restrict__ Wm) {
    int i = blockIdx.x * blockDim.x + threadIdx.x;
    if (i < Hh * Cc * Ff) {  // Wcat[c, h*F+f] = W[h,c,f]
        int f = i % Ff; int rest = i / Ff;
        int c = rest % Cc; int h = rest / Cc;
        g_Wcat[c * HF + h * Ff + f] = W[(h * Cc + c) * Ff + f];
    }
    if (i < HF * Cc) {       // WgT[hf, o] = Wg[o, hf]
        int o = i % Cc; int hf = i / Cc;
        g_WgT[hf * Cc + o] = Wg[o * HF + hf];
    }
    if (i < 3 * Cc * Cc) {   // WmT[c, o] = Wm[o, c]
        int o = i % Cc; int c = i / Cc;
        g_WmT[c * Cc + o] = Wm[o * (3 * Cc) + c];
    }
}

// ---------------- tiled input transpose: x[b,c,n,t] -> xT[s,n,c] ----------------
__global__ void transpose_in(const float* __restrict__ x, float* __restrict__ xT) {
    __shared__ float sm[16][193];
    const int b = blockIdx.z, c0 = blockIdx.y * 16, n0 = blockIdx.x * 16;
    const int tt_ = threadIdx.x;            // 0..191
    const int ni_l = tt_ / 12, tl = tt_ % 12;
    const int n_l = n0 + ni_l;
    #pragma unroll
    for (int ci = 0; ci < 16; ++ci) {
        float v = 0.f;
        if (n_l < Nn)
            v = x[(((size_t)b * Cc + c0 + ci) * Nn + n_l) * Tt + tl];
        sm[ci][tt_] = v;
    }
    __syncthreads();
    #pragma unroll
    for (int rep = 0; rep < 16; ++rep) {
        int idx = rep * 192 + tt_;          // 0..3071
        int ci = idx & 15;
        int rest = idx >> 4;                // ni*12 + t
        int ni = rest / 12, t = rest % 12;
        int n = n0 + ni;
        if (n < Nn)
            xT[(((size_t)(b * Tt + t) * Nn) + n) * Cc + c0 + ci] = sm[ci][rest];
    }
}

// ================= fused-head tf32 proj GEMM + e1/e2 + fp16 Wh ======================
// grid (Ss, 8), block 256 (8 warps). Tile 64 rows x 256 cols (all 4 heads), K=64.
// dyn smem: As[64][72] + Bs[64][264] (B later reused as C tile).
#define AS_LD 72
#define BS_LD 264
#define SMEM_PROJ (64 * AS_LD * 4 + 64 * BS_LD * 4)

__global__ __launch_bounds__(256, 2)
void gemm_proj_tc(const float* __restrict__ A,
                  const float* __restrict__ a1,
                  const float* __restrict__ a2) {
    extern __shared__ float smemBuf[];
    float (*As)[AS_LD] = (float(*)[AS_LD])smemBuf;
    float (*Bs)[BS_LD] = (float(*)[BS_LD])(smemBuf + 64 * AS_LD);
    __shared__ float sA1[HF], sA2[HF];

    const int s = blockIdx.x;
    const int r0 = blockIdx.y * 64;
    const float* Asl = A + (size_t)s * Nn * Cc;
    const int tid = threadIdx.x;
    const int wid = tid >> 5;
    const int wm = wid & 3, wn = wid >> 2;   // rows wm*16, cols wn*128

    if (tid < HF) { sA1[tid] = a1[tid]; sA2[tid] = a2[tid]; }
    #pragma unroll 4
    for (int i = tid; i < 64 * 64; i += 256) {
        int r = i >> 6, k = i & 63;
        int row = r0 + r;
        As[r][k] = (row < Nn) ? Asl[(size_t)row * Cc + k] : 0.f;
    }
    #pragma unroll 4
    for (int i = tid; i < 64 * 256; i += 256) {
        int k = i >> 8, c = i & 255;
        Bs[k][c] = g_Wcat[k * HF + c];
    }
    __syncthreads();

    wmma::fragment<wmma::accumulator, 16, 16, 8, float> fc[8];
    #pragma unroll
    for (int j = 0; j < 8; ++j) wmma::fill_fragment(fc[j], 0.f);

    #pragma unroll
    for (int k0 = 0; k0 < 64; k0 += 8) {
        wmma::fragment<wmma::matrix_a, 16, 16, 8, wmma::precision::tf32, wmma::row_major> fa;
        wmma::load_matrix_sync(fa, &As[wm * 16][k0], AS_LD);
        #pragma unroll
        for (int i = 0; i < fa.num_elements; ++i) fa.x[i] = wmma::__float_to_tf32(fa.x[i]);
        #pragma unroll
        for (int j = 0; j < 8; ++j) {
            wmma::fragment<wmma::matrix_b, 16, 16, 8, wmma::precision::tf32, wmma::row_major> fb;
            wmma::load_matrix_sync(fb, &Bs[k0][wn * 128 + j * 16], BS_LD);
            #pragma unroll
            for (int i = 0; i < fb.num_elements; ++i) fb.x[i] = wmma::__float_to_tf32(fb.x[i]);
            wmma::mma_sync(fc[j], fa, fb, fc[j]);
        }
    }
    __syncthreads();   // done reading Bs; reuse as C tile
    #pragma unroll
    for (int j = 0; j < 8; ++j)
        wmma::store_matrix_sync(&Bs[wm * 16][wn * 128 + j * 16], fc[j], BS_LD,
                                wmma::mem_row_major);
    __syncthreads();

    // e1/e2: thread -> (row = tid>>2, head = tid&3); each owns a full 64-col head segment
    {
        const int row = tid >> 2, h = tid & 3;
        float s1 = 0.f, s2 = 0.f;
        #pragma unroll
        for (int i = 0; i < Ff; ++i) {
            float v = Bs[row][h * Ff + i];
            s1 = fmaf(v, sA1[h * Ff + i], s1);
            s2 = fmaf(v, sA2[h * Ff + i], s2);
        }
        if (r0 + row < Nn) {
            const int sh = s * Hh + h;
            g_e1[sh * Nn + r0 + row] = s1;
            g_e2[sh * Nn + r0 + row] = s2;
        }
    }

    // fp16 Wh store (coalesced): 64 rows x 128 half2
    #pragma unroll
    for (int k = 0; k < 32; ++k) {
        int idx = k * 256 + tid;
        int r = idx >> 7, p = idx & 127;
        if (r0 + r < Nn) {
            g_Wh16[((size_t)s * Nn + r0 + r) * (HF / 2) + p] =
                __floats2half2_rn(Bs[r][2 * p], Bs[r][2 * p + 1]);
        }
    }
}

// ================= tf32 wmma mix GEMM: h_next = a*x + (1-a)*(hpr @ WgT + bg) =========
__global__ void gemm_mix_tc(const float* __restrict__ Ain,
                            const float* __restrict__ bias,
                            const float* __restrict__ resid,
                            float* __restrict__ Cm) {
    __shared__ __align__(32) float As[64][72];
    __shared__ __align__(32) float Bs[64][72];
    const int s = blockIdx.x;
    const int r0 = blockIdx.y * 64;
    const float* Asl = Ain + (size_t)s * Nn * HF;
    const int tid = threadIdx.x;
    const int wid = tid >> 5;
    const int wm = wid & 3, wn = wid >> 2;

    wmma::fragment<wmma::accumulator, 16, 16, 8, float> fc[2];
    wmma::fill_fragment(fc[0], 0.f);
    wmma::fill_fragment(fc[1], 0.f);

    for (int kb = 0; kb < HF; kb += 64) {
        #pragma unroll 4
        for (int i = tid; i < 64 * 64; i += 256) {
            int r = i >> 6, k = i & 63;
            int row = r0 + r;
            As[r][k] = (row < Nn) ? Asl[(size_t)row * HF + kb + k] : 0.f;
        }
        #pragma unroll 4
        for (int i = tid; i < 64 * 64; i += 256) {
            int k = i >> 6, c = i & 63;
            Bs[k][c] = g_WgT[(kb + k) * Cc + c];
        }
        __syncthreads();
        #pragma unroll
        for (int k0 = 0; k0 < 64; k0 += 8) {
            wmma::fragment<wmma::matrix_a, 16, 16, 8, wmma::precision::tf32, wmma::row_major> fa;
            wmma::load_matrix_sync(fa, &As[wm * 16][k0], 72);
            #pragma unroll
            for (int i = 0; i < fa.num_elements; ++i) fa.x[i] = wmma::__float_to_tf32(fa.x[i]);
            #pragma unroll
            for (int sub = 0; sub < 2; ++sub) {
                wmma::fragment<wmma::matrix_b, 16, 16, 8, wmma::precision::tf32, wmma::row_major> fb;
                wmma::load_matrix_sync(fb, &Bs[k0][wn * 32 + sub * 16], 72);
                #pragma unroll
                for (int i = 0; i < fb.num_elements; ++i) fb.x[i] = wmma::__float_to_tf32(fb.x[i]);
                wmma::mma_sync(fc[sub], fa, fb, fc[sub]);
            }
        }
        __syncthreads();
    }
    wmma::store_matrix_sync(&As[wm * 16][wn * 32], fc[0], 72, wmma::mem_row_major);
    wmma::store_matrix_sync(&As[wm * 16][wn * 32 + 16], fc[1], 72, wmma::mem_row_major);
    __syncthreads();

    #pragma unroll
    for (int k = 0; k < 16; ++k) {
        int idx = k * 256 + tid;
        int r = idx >> 6, c = idx & 63;
        int row = r0 + r;
        if (row < Nn) {
            size_t oidx = ((size_t)s * Nn + row) * Cc + c;
            Cm[oidx] = ALPHAc * resid[oidx] + (1.f - ALPHAc) * (As[r][c] + bias[c]);
        }
    }
}

// ---------------- attention softmax + uint4 gather aggregation ----------------
// block per (n,s), 128 threads. Phase1: warp-per-head softmax.
// Phase2: 4 neighbor lanes (g) x 32 chunks (c, 16B each) gather; cross-warp reduce.
__global__ void attn_agg(float* __restrict__ hpr) {
    const int n = blockIdx.x, s = blockIdx.y;
    const int t = threadIdx.x;
    const int h = t >> 5, lane = t & 31;
    __shared__ int snbr[MAXD];
    __shared__ float sw[Hh][MAXD];
    __shared__ float sred[4][HF];

    const int cnt = min(g_cnt[n], MAXD);
    for (int j = t; j < cnt; j += 128) snbr[j] = g_nbr[n * MAXD + j];
    __syncthreads();

    // phase 1: softmax over neighbors for head h (warp h)
    const int sh = s * Hh + h;
    const float e1v = g_e1[sh * Nn + n];
    const float* e2r = g_e2 + (size_t)sh * Nn;
    float ev[4];
    float mx = -1e30f;
    #pragma unroll
    for (int k = 0; k < 4; ++k) {
        int j = k * 32 + lane;
        float e = -1e30f;
        if (j < cnt) {
            float tv = e1v + e2r[snbr[j]];
            e = tv > 0.f ? tv : LEAKc * tv;
        }
        ev[k] = e;
        mx = fmaxf(mx, e);
    }
    #pragma unroll
    for (int o = 16; o; o >>= 1) mx = fmaxf(mx, __shfl_xor_sync(0xffffffffu, mx, o));
    float sum = 0.f;
    #pragma unroll
    for (int k = 0; k < 4; ++k) {
        float w = (k * 32 + lane < cnt) ? __expf(ev[k] - mx) : 0.f;
        ev[k] = w;
        sum += w;
    }
    #pragma unroll
    for (int o = 16; o; o >>= 1) sum += __shfl_xor_sync(0xffffffffu, sum, o);
    const float inv = 1.f / sum;
    #pragma unroll
    for (int k = 0; k < 4; ++k) {
        int j = k * 32 + lane;
        if (j < cnt) sw[h][j] = ev[k] * inv;
    }
    __syncthreads();

    // phase 2: thread (g = t>>5, c = t&31); chunk c = 16B = 8 halfs of the 512B row
    const int g = t >> 5, c = t & 31;
    const int hc = c >> 3;                 // head of this chunk
    const size_t rowB = (size_t)s * Nn;
    const uint4* Whv = (const uint4*)g_Wh16;
    float acc[8] = {};
    #pragma unroll 2
    for (int j0 = 0; j0 < cnt; j0 += 4) {
        int j = j0 + g;
        if (j < cnt) {
            int m = snbr[j];
            float w = sw[hc][j];
            uint4 v = Whv[(rowB + m) * 32 + c];
            float2 f0 = __half22float2(*(__half2*)&v.x);
            float2 f1 = __half22float2(*(__half2*)&v.y);
            float2 f2 = __half22float2(*(__half2*)&v.z);
            float2 f3 = __half22float2(*(__half2*)&v.w);
            acc[0] = fmaf(w, f0.x, acc[0]); acc[1] = fmaf(w, f0.y, acc[1]);
            acc[2] = fmaf(w, f1.x, acc[2]); acc[3] = fmaf(w, f1.y, acc[3]);
            acc[4] = fmaf(w, f2.x, acc[4]); acc[5] = fmaf(w, f2.y, acc[5]);
            acc[6] = fmaf(w, f3.x, acc[6]); acc[7] = fmaf(w, f3.y, acc[7]);
        }
    }
    #pragma unroll
    for (int i = 0; i < 8; ++i) sred[g][c * 8 + i] = acc[i];
    __syncthreads();

    // reduce 4 partials, elu, store (thread t -> hf {2t, 2t+1})
    float vx = sred[0][2 * t]     + sred[1][2 * t]     + sred[2][2 * t]     + sred[3][2 * t];
    float vy = sred[0][2 * t + 1] + sred[1][2 * t + 1] + sred[2][2 * t + 1] + sred[3][2 * t + 1];
    float2 o2;
    o2.x = vx > 0.f ? vx : (__expf(vx) - 1.f);
    o2.y = vy > 0.f ? vy : (__expf(vy) - 1.f);
    ((float2*)hpr)[(rowB + n) * (HF / 2) + t] = o2;
}

// ---------------- final: out[b,o,n,t] = bm[o] + Wm @ [x; h1; h2] (exact fp32) ----------
__global__ void final_out(const float* __restrict__ xT,
                          const float* __restrict__ h1,
                          const float* __restrict__ h2,
                          const float* __restrict__ bm,
                          float* __restrict__ out) {
    __shared__ float sX[16][64], sH1[16][64], sH2[16][64];
    const int s = blockIdx.x;
    const int n0 = blockIdx.y * 16;
    const int tid = threadIdx.x;
    for (int i = tid; i < 16 * 64; i += 256) {
        int nl = i >> 6, c = i & 63;
        int n = n0 + nl;
        size_t idx = ((size_t)s * Nn + (n < Nn ? n : 0)) * Cc + c;
        sX[nl][c]  = (n < Nn) ? xT[idx] : 0.f;
        sH1[nl][c] = (n < Nn) ? h1[idx] : 0.f;
        sH2[nl][c] = (n < Nn) ? h2[idx] : 0.f;
    }
    __syncthreads();
    const int o = tid & 63, ng = tid >> 6;
    float acc[4] = {0.f, 0.f, 0.f, 0.f};
    #pragma unroll 4
    for (int c = 0; c < 64; ++c) {
        float w0 = g_WmT[c * Cc + o];
        float w1 = g_WmT[(64 + c) * Cc + o];
        float w2 = g_WmT[(128 + c) * Cc + o];
        #pragma unroll
        for (int r = 0; r < 4; ++r) {
            int nl = ng + r * 4;
            acc[r] = fmaf(w0, sX[nl][c], fmaf(w1, sH1[nl][c], fmaf(w2, sH2[nl][c], acc[r])));
        }
    }
    const int b = s / Tt, t = s % Tt;
    const float bias = bm[o];
    #pragma unroll
    for (int r = 0; r < 4; ++r) {
        int n = n0 + ng + r * 4;
        if (n < Nn)
            out[(((size_t)b * Cc + o) * Nn + n) * Tt + t] = acc[r] + bias;
    }
}

// ---------------- launch ----------------
extern "C" void kernel_launch(void* const* d_in, const int* in_sizes, int n_in,
                              void* d_out, int out_size) {
    const float* x   = (const float*)d_in[0];
    const float* adj = (const float*)d_in[1];
    const float* W   = (const float*)d_in[2];
    const float* a1  = (const float*)d_in[3];
    const float* a2  = (const float*)d_in[4];
    const float* Wg  = (const float*)d_in[5];
    const float* bg  = (const float*)d_in[6];
    const float* Wm  = (const float*)d_in[7];
    const float* bm  = (const float*)d_in[8];
    float* out = (float*)d_out;

    float *xT, *h1T, *h2T, *hpr;
    cudaGetSymbolAddress((void**)&xT,  g_xT);
    cudaGetSymbolAddress((void**)&h1T, g_h1T);
    cudaGetSymbolAddress((void**)&h2T, g_h2T);
    cudaGetSymbolAddress((void**)&hpr, g_hpr);

    static bool attr_set = false;
    if (!attr_set) {
        cudaFuncSetAttribute(gemm_proj_tc,
                             cudaFuncAttributeMaxDynamicSharedMemorySize, SMEM_PROJ);
        attr_set = true;
    }

    build_nbr<<<125, 128>>>(adj);
    prep_weights<<<64, 256>>>(W, Wg, Wm);
    transpose_in<<<dim3(32, 4, Bb), 192>>>(x, xT);

    const float* hin = xT;
    float* hb[2] = {h1T, h2T};
    for (int it = 0; it < 2; ++it) {
        gemm_proj_tc<<<dim3(Ss, 8), 256, SMEM_PROJ>>>(hin, a1, a2);
        attn_agg<<<dim3(Nn, Ss), 128>>>(hpr);
        gemm_mix_tc<<<dim3(Ss, 8), 256>>>(hpr, bg, xT, hb[it]);
        hin = hb[it];
    }
    final_out<<<dim3(Ss, (Nn + 15) / 16), 256>>>(xT, h1T, h2T, bm, out);
}

// round 5
// speedup vs baseline: 1.3172x; 1.3107x over previous
#include <cuda_runtime.h>
#include <cuda_fp16.h>
#include <mma.h>
#include <cstdint>

using namespace nvcuda;

// Problem constants
#define Bb 8
#define Cc 64
#define Nn 500
#define Tt 12
#define Hh 4
#define Ff 64
#define Ss (Bb * Tt)   // 96 slices (b,t)
#define HF (Hh * Ff)   // 256
#define MAXD 128
#define ALPHAc 0.05f
#define LEAKc 0.2f

// ---------------- scratch (device globals; no allocation) ----------------
__device__ float   g_xT[Ss * Nn * Cc];                 // [s,n,c]
__device__ float   g_h1T[Ss * Nn * Cc];
__device__ float   g_h2T[Ss * Nn * Cc];
__device__ __half2 g_Wh16[(size_t)Ss * Nn * (HF / 2)]; // [s,n,hf/2] fp16 pairs
__device__ __half2 g_hpr16[(size_t)Ss * Nn * (HF / 2)];// [s,n,hf/2] fp16 pairs
__device__ float   g_e1[Ss * Hh * Nn];                 // [(s*H+h)*N + n]
__device__ float   g_e2[Ss * Hh * Nn];
__device__ float   g_Wcat[Cc * HF];                    // [c, h*F+f]
__device__ __half  g_WgT16[HF * Cc];                   // [hf, o] fp16
__device__ float   g_WmT[3 * Cc * Cc];                 // [c_global, o]
__device__ int     g_cnt[Nn];
__device__ int     g_nbr[Nn * MAXD];

// ================= merged prep: nbr list + weight layouts + input transpose =========
// blocks [0,125): build_nbr (4 warps each, uses 128 threads)
// blocks [125,189): weight re-layouts (64 blocks x 256)
// blocks [189,1213): tiled transpose (uses 192 threads)
__global__ void prep_all(const float* __restrict__ adj,
                         const float* __restrict__ W,
                         const float* __restrict__ Wg,
                         const float* __restrict__ Wm,
                         const float* __restrict__ x,
                         float* __restrict__ xT) {
    __shared__ float sm[16][193];
    const int blk = blockIdx.x;
    if (blk < 125) {
        if (threadIdx.x >= 128) return;
        int warp = threadIdx.x >> 5;
        int lane = threadIdx.x & 31;
        int n = blk * 4 + warp;
        if (n >= Nn) return;
        int base = 0;
        for (int m0 = 0; m0 < 512; m0 += 32) {
            int m = m0 + lane;
            bool p = (m < Nn) && (adj[n * Nn + m] > 0.f || m == n);
            unsigned mask = __ballot_sync(0xffffffffu, p);
            if (p) {
                int r = __popc(mask & ((1u << lane) - 1));
                if (base + r < MAXD) g_nbr[n * MAXD + base + r] = m;
            }
            base += __popc(mask);
        }
        if (lane == 0) g_cnt[n] = base < MAXD ? base : MAXD;
    } else if (blk < 189) {
        int i = (blk - 125) * 256 + threadIdx.x;
        if (i < Hh * Cc * Ff) {  // Wcat[c, h*F+f] = W[h,c,f]
            int f = i % Ff; int rest = i / Ff;
            int c = rest % Cc; int h = rest / Cc;
            g_Wcat[c * HF + h * Ff + f] = W[(h * Cc + c) * Ff + f];
        }
        if (i < HF * Cc) {       // WgT16[hf, o] = half(Wg[o, hf])
            int o = i % Cc; int hf = i / Cc;
            g_WgT16[hf * Cc + o] = __float2half_rn(Wg[o * HF + hf]);
        }
        if (i < 3 * Cc * Cc) {   // WmT[c, o] = Wm[o, c]
            int o = i % Cc; int c = i / Cc;
            g_WmT[c * Cc + o] = Wm[o * (3 * Cc) + c];
        }
    } else {
        // transpose: x[b,c,n,t] -> xT[s,n,c]
        if (threadIdx.x >= 192) return;
        const int bi = blk - 189;
        const int nb = bi & 31, cb = (bi >> 5) & 3, b = bi >> 7;
        const int c0 = cb * 16, n0 = nb * 16;
        const int tt_ = threadIdx.x;
        const int ni_l = tt_ / 12, tl = tt_ % 12;
        const int n_l = n0 + ni_l;
        #pragma unroll
        for (int ci = 0; ci < 16; ++ci) {
            float v = 0.f;
            if (n_l < Nn)
                v = x[(((size_t)b * Cc + c0 + ci) * Nn + n_l) * Tt + tl];
            sm[ci][tt_] = v;
        }
        __syncthreads();
        #pragma unroll
        for (int rep = 0; rep < 16; ++rep) {
            int idx = rep * 192 + tt_;
            int ci = idx & 15;
            int rest = idx >> 4;
            int ni = rest / 12, t = rest % 12;
            int n = n0 + ni;
            if (n < Nn)
                xT[(((size_t)(b * Tt + t) * Nn) + n) * Cc + c0 + ci] = sm[ci][rest];
        }
    }
}

// ================= tf32 wmma projection GEMM + fused e1/e2 + fp16 Wh =================
// grid (Ss, 8, Hh), block 256 (8 warps). Tile 64x64, K=64.
__global__ void gemm_proj_tc(const float* __restrict__ A,
                             const float* __restrict__ a1,
                             const float* __restrict__ a2) {
    __shared__ __align__(32) float As[64][72];
    __shared__ __align__(32) float Bs[64][72];
    const int s = blockIdx.x;
    const int r0 = blockIdx.y * 64;
    const int h = blockIdx.z;
    const int c0 = h * 64;
    const float* Asl = A + (size_t)s * Nn * Cc;
    const int tid = threadIdx.x;
    const int wid = tid >> 5;
    const int wm = wid & 3, wn = wid >> 2;   // warp tile: rows wm*16, cols wn*32

    #pragma unroll 4
    for (int i = tid; i < 64 * 64; i += 256) {
        int r = i >> 6, k = i & 63;
        int row = r0 + r;
        As[r][k] = (row < Nn) ? Asl[(size_t)row * Cc + k] : 0.f;
    }
    #pragma unroll 4
    for (int i = tid; i < 64 * 64; i += 256) {
        int k = i >> 6, c = i & 63;
        Bs[k][c] = g_Wcat[k * HF + c0 + c];
    }
    __syncthreads();

    wmma::fragment<wmma::accumulator, 16, 16, 8, float> fc[2];
    wmma::fill_fragment(fc[0], 0.f);
    wmma::fill_fragment(fc[1], 0.f);
    #pragma unroll
    for (int k0 = 0; k0 < 64; k0 += 8) {
        wmma::fragment<wmma::matrix_a, 16, 16, 8, wmma::precision::tf32, wmma::row_major> fa;
        wmma::load_matrix_sync(fa, &As[wm * 16][k0], 72);
        #pragma unroll
        for (int i = 0; i < fa.num_elements; ++i) fa.x[i] = wmma::__float_to_tf32(fa.x[i]);
        #pragma unroll
        for (int sub = 0; sub < 2; ++sub) {
            wmma::fragment<wmma::matrix_b, 16, 16, 8, wmma::precision::tf32, wmma::row_major> fb;
            wmma::load_matrix_sync(fb, &Bs[k0][wn * 32 + sub * 16], 72);
            #pragma unroll
            for (int i = 0; i < fb.num_elements; ++i) fb.x[i] = wmma::__float_to_tf32(fb.x[i]);
            wmma::mma_sync(fc[sub], fa, fb, fc[sub]);
        }
    }
    __syncthreads();   // done reading As/Bs
    wmma::store_matrix_sync(&As[wm * 16][wn * 32], fc[0], 72, wmma::mem_row_major);
    wmma::store_matrix_sync(&As[wm * 16][wn * 32 + 16], fc[1], 72, wmma::mem_row_major);
    __syncthreads();

    // fused e1/e2: thread t -> row t>>2, quarter t&3 (16 cols each); reduce over 4 lanes
    {
        const int row = tid >> 2, q = tid & 3;
        float s1 = 0.f, s2 = 0.f;
        #pragma unroll
        for (int i = 0; i < 16; ++i) {
            int c = q * 16 + i;
            float v = As[row][c];
            s1 = fmaf(v, a1[c0 + c], s1);
            s2 = fmaf(v, a2[c0 + c], s2);
        }
        s1 += __shfl_xor_sync(0xffffffffu, s1, 1);
        s2 += __shfl_xor_sync(0xffffffffu, s2, 1);
        s1 += __shfl_xor_sync(0xffffffffu, s1, 2);
        s2 += __shfl_xor_sync(0xffffffffu, s2, 2);
        if (q == 0 && r0 + row < Nn) {
            const int sh = s * Hh + h;
            g_e1[sh * Nn + r0 + row] = s1;
            g_e2[sh * Nn + r0 + row] = s2;
        }
    }

    // fp16 Wh store (coalesced): 64 rows x 32 half2
    #pragma unroll
    for (int k = 0; k < 8; ++k) {
        int idx = k * 256 + tid;
        int r = idx >> 5, p = idx & 31;
        if (r0 + r < Nn) {
            g_Wh16[((size_t)s * Nn + r0 + r) * (HF / 2) + (c0 >> 1) + p] =
                __floats2half2_rn(As[r][2 * p], As[r][2 * p + 1]);
        }
    }
}

// ---------------- attention softmax + uint4 gather aggregation (fp16 out) ------------
__global__ void attn_agg() {
    const int n = blockIdx.x, s = blockIdx.y;
    const int t = threadIdx.x;
    const int h = t >> 5, lane = t & 31;
    __shared__ int snbr[MAXD];
    __shared__ float sw[Hh][MAXD];
    __shared__ float sred[4][HF];

    const int cnt = min(g_cnt[n], MAXD);
    for (int j = t; j < cnt; j += 128) snbr[j] = g_nbr[n * MAXD + j];
    __syncthreads();

    // phase 1: softmax over neighbors for head h (warp h)
    const int sh = s * Hh + h;
    const float e1v = g_e1[sh * Nn + n];
    const float* e2r = g_e2 + (size_t)sh * Nn;
    float ev[4];
    float mx = -1e30f;
    #pragma unroll
    for (int k = 0; k < 4; ++k) {
        int j = k * 32 + lane;
        float e = -1e30f;
        if (j < cnt) {
            float tv = e1v + e2r[snbr[j]];
            e = tv > 0.f ? tv : LEAKc * tv;
        }
        ev[k] = e;
        mx = fmaxf(mx, e);
    }
    #pragma unroll
    for (int o = 16; o; o >>= 1) mx = fmaxf(mx, __shfl_xor_sync(0xffffffffu, mx, o));
    float sum = 0.f;
    #pragma unroll
    for (int k = 0; k < 4; ++k) {
        float w = (k * 32 + lane < cnt) ? __expf(ev[k] - mx) : 0.f;
        ev[k] = w;
        sum += w;
    }
    #pragma unroll
    for (int o = 16; o; o >>= 1) sum += __shfl_xor_sync(0xffffffffu, sum, o);
    const float inv = 1.f / sum;
    #pragma unroll
    for (int k = 0; k < 4; ++k) {
        int j = k * 32 + lane;
        if (j < cnt) sw[h][j] = ev[k] * inv;
    }
    __syncthreads();

    // phase 2: thread (g = t>>5, c = t&31); chunk c = 16B = 8 halfs of the 512B row
    const int g = t >> 5, c = t & 31;
    const int hc = c >> 3;                 // head of this chunk
    const size_t rowB = (size_t)s * Nn;
    const uint4* Whv = (const uint4*)g_Wh16;
    float acc[8] = {};
    #pragma unroll 2
    for (int j0 = 0; j0 < cnt; j0 += 4) {
        int j = j0 + g;
        if (j < cnt) {
            int m = snbr[j];
            float w = sw[hc][j];
            uint4 v = Whv[(rowB + m) * 32 + c];
            float2 f0 = __half22float2(*(__half2*)&v.x);
            float2 f1 = __half22float2(*(__half2*)&v.y);
            float2 f2 = __half22float2(*(__half2*)&v.z);
            float2 f3 = __half22float2(*(__half2*)&v.w);
            acc[0] = fmaf(w, f0.x, acc[0]); acc[1] = fmaf(w, f0.y, acc[1]);
            acc[2] = fmaf(w, f1.x, acc[2]); acc[3] = fmaf(w, f1.y, acc[3]);
            acc[4] = fmaf(w, f2.x, acc[4]); acc[5] = fmaf(w, f2.y, acc[5]);
            acc[6] = fmaf(w, f3.x, acc[6]); acc[7] = fmaf(w, f3.y, acc[7]);
        }
    }
    #pragma unroll
    for (int i = 0; i < 8; ++i) sred[g][c * 8 + i] = acc[i];
    __syncthreads();

    // reduce 4 partials, elu, fp16 store (thread t -> hf {2t, 2t+1})
    float vx = sred[0][2 * t]     + sred[1][2 * t]     + sred[2][2 * t]     + sred[3][2 * t];
    float vy = sred[0][2 * t + 1] + sred[1][2 * t + 1] + sred[2][2 * t + 1] + sred[3][2 * t + 1];
    vx = vx > 0.f ? vx : (__expf(vx) - 1.f);
    vy = vy > 0.f ? vy : (__expf(vy) - 1.f);
    g_hpr16[(rowB + n) * (HF / 2) + t] = __floats2half2_rn(vx, vy);
}

// ================= fp16 wmma mix GEMM: h_next = a*x + (1-a)*(hpr16 @ WgT16 + bg) =====
// grid (Ss, 8), block 256 (8 warps). Single-stage: As 64x256 half, Bs 256x64 half.
#define AS16_LD 272
#define BS16_LD 72
#define SMEM_MIX (64 * AS16_LD * 2 + 256 * BS16_LD * 2)

__global__ void gemm_mix_tc(const float* __restrict__ bias,
                            const float* __restrict__ resid,
                            float* __restrict__ Cm) {
    extern __shared__ __align__(16) char smemRaw[];
    __half (*As)[AS16_LD] = (__half(*)[AS16_LD])smemRaw;
    __half (*Bs)[BS16_LD] = (__half(*)[BS16_LD])(smemRaw + 64 * AS16_LD * 2);
    const int s = blockIdx.x;
    const int r0 = blockIdx.y * 64;
    const int tid = threadIdx.x;
    const int wid = tid >> 5;
    const int wm = wid & 3, wn = wid >> 2;

    // stage A: 64 rows x 256 halfs (row = 32 uint4), 8 uint4/thread
    {
        const uint4* src = (const uint4*)(g_hpr16 + (size_t)s * Nn * (HF / 2));
        #pragma unroll
        for (int k = 0; k < 8; ++k) {
            int idx = k * 256 + tid;          // 0..2047
            int r = idx >> 5, p = idx & 31;
            int row = r0 + r;
            uint4 v = make_uint4(0, 0, 0, 0);
            if (row < Nn) v = src[(size_t)row * 32 + p];
            *(uint4*)&As[r][p * 8] = v;
        }
    }
    // stage B: 256 rows x 64 halfs (row = 8 uint4), 8 uint4/thread
    {
        const uint4* src = (const uint4*)g_WgT16;
        #pragma unroll
        for (int k = 0; k < 8; ++k) {
            int idx = k * 256 + tid;          // 0..2047
            int r = idx >> 3, p = idx & 7;
            *(uint4*)&Bs[r][p * 8] = src[r * 8 + p];
        }
    }
    __syncthreads();

    wmma::fragment<wmma::accumulator, 16, 16, 16, float> fc[2];
    wmma::fill_fragment(fc[0], 0.f);
    wmma::fill_fragment(fc[1], 0.f);
    #pragma unroll
    for (int k0 = 0; k0 < 256; k0 += 16) {
        wmma::fragment<wmma::matrix_a, 16, 16, 16, __half, wmma::row_major> fa;
        wmma::load_matrix_sync(fa, &As[wm * 16][k0], AS16_LD);
        #pragma unroll
        for (int sub = 0; sub < 2; ++sub) {
            wmma::fragment<wmma::matrix_b, 16, 16, 16, __half, wmma::row_major> fb;
            wmma::load_matrix_sync(fb, &Bs[k0][wn * 32 + sub * 16], BS16_LD);
            wmma::mma_sync(fc[sub], fa, fb, fc[sub]);
        }
    }
    __syncthreads();
    float* Cs = (float*)smemRaw;              // 64 x 68 floats (17.4KB) over As region
    wmma::store_matrix_sync(&Cs[(wm * 16) * 68 + wn * 32], fc[0], 68, wmma::mem_row_major);
    wmma::store_matrix_sync(&Cs[(wm * 16) * 68 + wn * 32 + 16], fc[1], 68, wmma::mem_row_major);
    __syncthreads();

    #pragma unroll
    for (int k = 0; k < 16; ++k) {
        int idx = k * 256 + tid;
        int r = idx >> 6, c = idx & 63;
        int row = r0 + r;
        if (row < Nn) {
            size_t oidx = ((size_t)s * Nn + row) * Cc + c;
            Cm[oidx] = ALPHAc * resid[oidx] + (1.f - ALPHAc) * (Cs[r * 68 + c] + bias[c]);
        }
    }
}

// ---------------- final: out[b,o,n,t] = bm[o] + Wm @ [x; h1; h2] (exact fp32) ----------
__global__ void final_out(const float* __restrict__ xT,
                          const float* __restrict__ h1,
                          const float* __restrict__ h2,
                          const float* __restrict__ bm,
                          float* __restrict__ out) {
    __shared__ float sX[16][64], sH1[16][64], sH2[16][64];
    const int s = blockIdx.x;
    const int n0 = blockIdx.y * 16;
    const int tid = threadIdx.x;
    for (int i = tid; i < 16 * 64; i += 256) {
        int nl = i >> 6, c = i & 63;
        int n = n0 + nl;
        size_t idx = ((size_t)s * Nn + (n < Nn ? n : 0)) * Cc + c;
        sX[nl][c]  = (n < Nn) ? xT[idx] : 0.f;
        sH1[nl][c] = (n < Nn) ? h1[idx] : 0.f;
        sH2[nl][c] = (n < Nn) ? h2[idx] : 0.f;
    }
    __syncthreads();
    const int o = tid & 63, ng = tid >> 6;
    float acc[4] = {0.f, 0.f, 0.f, 0.f};
    #pragma unroll 4
    for (int c = 0; c < 64; ++c) {
        float w0 = g_WmT[c * Cc + o];
        float w1 = g_WmT[(64 + c) * Cc + o];
        float w2 = g_WmT[(128 + c) * Cc + o];
        #pragma unroll
        for (int r = 0; r < 4; ++r) {
            int nl = ng + r * 4;
            acc[r] = fmaf(w0, sX[nl][c], fmaf(w1, sH1[nl][c], fmaf(w2, sH2[nl][c], acc[r])));
        }
    }
    const int b = s / Tt, t = s % Tt;
    const float bias = bm[o];
    #pragma unroll
    for (int r = 0; r < 4; ++r) {
        int n = n0 + ng + r * 4;
        if (n < Nn)
            out[(((size_t)b * Cc + o) * Nn + n) * Tt + t] = acc[r] + bias;
    }
}

// ---------------- launch ----------------
extern "C" void kernel_launch(void* const* d_in, const int* in_sizes, int n_in,
                              void* d_out, int out_size) {
    const float* x   = (const float*)d_in[0];
    const float* adj = (const float*)d_in[1];
    const float* W   = (const float*)d_in[2];
    const float* a1  = (const float*)d_in[3];
    const float* a2  = (const float*)d_in[4];
    const float* Wg  = (const float*)d_in[5];
    const float* bg  = (const float*)d_in[6];
    const float* Wm  = (const float*)d_in[7];
    const float* bm  = (const float*)d_in[8];
    float* out = (float*)d_out;

    float *xT, *h1T, *h2T;
    cudaGetSymbolAddress((void**)&xT,  g_xT);
    cudaGetSymbolAddress((void**)&h1T, g_h1T);
    cudaGetSymbolAddress((void**)&h2T, g_h2T);

    static bool attr_set = false;
    if (!attr_set) {
        cudaFuncSetAttribute(gemm_mix_tc,
                             cudaFuncAttributeMaxDynamicSharedMemorySize, SMEM_MIX);
        attr_set = true;
    }

    prep_all<<<1213, 256>>>(adj, W, Wg, Wm, x, xT);

    const float* hin = xT;
    float* hb[2] = {h1T, h2T};
    for (int it = 0; it < 2; ++it) {
        gemm_proj_tc<<<dim3(Ss, 8, Hh), 256>>>(hin, a1, a2);
        attn_agg<<<dim3(Nn, Ss), 128>>>();
        gemm_mix_tc<<<dim3(Ss, 8), 256, SMEM_MIX>>>(bg, xT, hb[it]);
        hin = hb[it];
    }
    final_out<<<dim3(Ss, (Nn + 15) / 16), 256>>>(xT, h1T, h2T, bm, out);
}

// round 6
// speedup vs baseline: 1.4610x; 1.1092x over previous
#include <cuda_runtime.h>
#include <cuda_fp16.h>
#include <mma.h>
#include <cstdint>

using namespace nvcuda;

// Problem constants
#define Bb 8
#define Cc 64
#define Nn 500
#define Tt 12
#define Hh 4
#define Ff 64
#define Ss (Bb * Tt)   // 96 slices (b,t)
#define HF (Hh * Ff)   // 256
#define MAXD 128
#define ROWPAD 16
#define ALPHAc 0.05f
#define LEAKc 0.2f

// ---------------- scratch (device globals; no allocation) ----------------
__device__ float   g_xT[Ss * Nn * Cc];                   // [s,n,c] fp32 (final path)
__device__ float   g_h1T[Ss * Nn * Cc];
__device__ float   g_h2T[Ss * Nn * Cc];
__device__ __half  g_xT16[Ss * Nn * Cc];                 // fp16 iterates (proj A input)
__device__ __half  g_h1T16[Ss * Nn * Cc];
__device__ __half  g_h2T16[Ss * Nn * Cc];
__device__ __half  g_Wh16[(size_t)Ss * Nn * HF];         // [s,n,hf] fp16
__device__ __half  g_hpr16[((size_t)Ss * Nn + ROWPAD) * HF]; // padded for OOB frag rows
__device__ float   g_e1[Ss * Hh * Nn];                   // [(s*H+h)*N + n]
__device__ float   g_e2[Ss * Hh * Nn];
__device__ __half  g_Wcat16[Cc * HF];                    // [c, h*F+f] fp16
__device__ __half  g_WgT16[HF * Cc];                     // [hf, o] fp16
__device__ float   g_WmT[3 * Cc * Cc];                   // [c_global, o]
__device__ int     g_cnt[Nn];
__device__ int     g_nbr[Nn * MAXD];

// ================= merged prep: nbr list + weight layouts + input transpose =========
__global__ void prep_all(const float* __restrict__ adj,
                         const float* __restrict__ W,
                         const float* __restrict__ Wg,
                         const float* __restrict__ Wm,
                         const float* __restrict__ x,
                         float* __restrict__ xT) {
    __shared__ float sm[16][193];
    const int blk = blockIdx.x;
    if (blk < 125) {
        if (threadIdx.x >= 128) return;
        int warp = threadIdx.x >> 5;
        int lane = threadIdx.x & 31;
        int n = blk * 4 + warp;
        if (n >= Nn) return;
        int base = 0;
        for (int m0 = 0; m0 < 512; m0 += 32) {
            int m = m0 + lane;
            bool p = (m < Nn) && (adj[n * Nn + m] > 0.f || m == n);
            unsigned mask = __ballot_sync(0xffffffffu, p);
            if (p) {
                int r = __popc(mask & ((1u << lane) - 1));
                if (base + r < MAXD) g_nbr[n * MAXD + base + r] = m;
            }
            base += __popc(mask);
        }
        if (lane == 0) g_cnt[n] = base < MAXD ? base : MAXD;
    } else if (blk < 189) {
        int i = (blk - 125) * 256 + threadIdx.x;
        if (i < Hh * Cc * Ff) {  // Wcat16[c, h*F+f] = W[h,c,f]
            int f = i % Ff; int rest = i / Ff;
            int c = rest % Cc; int h = rest / Cc;
            g_Wcat16[c * HF + h * Ff + f] = __float2half_rn(W[(h * Cc + c) * Ff + f]);
        }
        if (i < HF * Cc) {       // WgT16[hf, o] = half(Wg[o, hf])
            int o = i % Cc; int hf = i / Cc;
            g_WgT16[hf * Cc + o] = __float2half_rn(Wg[o * HF + hf]);
        }
        if (i < 3 * Cc * Cc) {   // WmT[c, o] = Wm[o, c]
            int o = i % Cc; int c = i / Cc;
            g_WmT[c * Cc + o] = Wm[o * (3 * Cc) + c];
        }
    } else {
        // transpose: x[b,c,n,t] -> xT[s,n,c] (fp32 + fp16)
        if (threadIdx.x >= 192) return;
        const int bi = blk - 189;
        const int nb = bi & 31, cb = (bi >> 5) & 3, b = bi >> 7;
        const int c0 = cb * 16, n0 = nb * 16;
        const int tt_ = threadIdx.x;
        const int ni_l = tt_ / 12, tl = tt_ % 12;
        const int n_l = n0 + ni_l;
        #pragma unroll
        for (int ci = 0; ci < 16; ++ci) {
            float v = 0.f;
            if (n_l < Nn)
                v = x[(((size_t)b * Cc + c0 + ci) * Nn + n_l) * Tt + tl];
            sm[ci][tt_] = v;
        }
        __syncthreads();
        #pragma unroll
        for (int rep = 0; rep < 16; ++rep) {
            int idx = rep * 192 + tt_;
            int ci = idx & 15;
            int rest = idx >> 4;
            int ni = rest / 12, t = rest % 12;
            int n = n0 + ni;
            if (n < Nn) {
                size_t oi = (((size_t)(b * Tt + t) * Nn) + n) * Cc + c0 + ci;
                float v = sm[ci][rest];
                xT[oi] = v;
                g_xT16[oi] = __float2half_rn(v);
            }
        }
    }
}

// ================= fp16 HMMA projection GEMM + fused e1/e2 + fp16 Wh ================
// grid (Ss, 8, Hh), block 256 (8 warps). Tile 64x64, K=64.
#define PAS_LD 72
__global__ void gemm_proj16(const __half* __restrict__ Ain,
                            const float* __restrict__ a1,
                            const float* __restrict__ a2) {
    __shared__ __align__(16) char smemRaw[2 * 64 * PAS_LD * 2];  // As+Bs, reused as Cs
    __half (*As)[PAS_LD] = (__half(*)[PAS_LD])smemRaw;
    __half (*Bs)[PAS_LD] = (__half(*)[PAS_LD])(smemRaw + 64 * PAS_LD * 2);
    float (*Cs)[68] = (float(*)[68])smemRaw;                     // 64*68*4 = 17408 <= 18432

    const int s = blockIdx.x;
    const int r0 = blockIdx.y * 64;
    const int h = blockIdx.z;
    const int c0 = h * 64;
    const int tid = threadIdx.x;
    const int wid = tid >> 5;
    const int wm = wid & 3, wn = wid >> 2;   // warp tile: rows wm*16, cols wn*32

    // stage A: 64 rows x 64 halfs (8 uint4/row), 2 uint4/thread
    {
        const uint4* srcA = (const uint4*)(Ain + (size_t)s * Nn * Cc);
        #pragma unroll
        for (int k = 0; k < 2; ++k) {
            int idx = k * 256 + tid;
            int r = idx >> 3, p = idx & 7;
            int row = r0 + r;
            uint4 v = make_uint4(0, 0, 0, 0);
            if (row < Nn) v = srcA[(size_t)row * 8 + p];
            *(uint4*)&As[r][p * 8] = v;
        }
    }
    // stage B: Wcat16 rows 0..63, cols c0..c0+63
    {
        const uint4* srcB = (const uint4*)(g_Wcat16 + c0);
        #pragma unroll
        for (int k = 0; k < 2; ++k) {
            int idx = k * 256 + tid;
            int r = idx >> 3, p = idx & 7;
            *(uint4*)&Bs[r][p * 8] = srcB[r * 32 + p];   // row stride 256 half = 32 uint4
        }
    }
    __syncthreads();

    wmma::fragment<wmma::accumulator, 16, 16, 16, float> fc[2];
    wmma::fill_fragment(fc[0], 0.f);
    wmma::fill_fragment(fc[1], 0.f);
    #pragma unroll
    for (int k0 = 0; k0 < 64; k0 += 16) {
        wmma::fragment<wmma::matrix_a, 16, 16, 16, __half, wmma::row_major> fa;
        wmma::load_matrix_sync(fa, &As[wm * 16][k0], PAS_LD);
        #pragma unroll
        for (int sub = 0; sub < 2; ++sub) {
            wmma::fragment<wmma::matrix_b, 16, 16, 16, __half, wmma::row_major> fb;
            wmma::load_matrix_sync(fb, &Bs[k0][wn * 32 + sub * 16], PAS_LD);
            wmma::mma_sync(fc[sub], fa, fb, fc[sub]);
        }
    }
    __syncthreads();   // done reading As/Bs; reuse as Cs
    wmma::store_matrix_sync(&Cs[wm * 16][wn * 32], fc[0], 68, wmma::mem_row_major);
    wmma::store_matrix_sync(&Cs[wm * 16][wn * 32 + 16], fc[1], 68, wmma::mem_row_major);
    __syncthreads();

    // fused e1/e2: thread -> row tid>>2, quarter tid&3 (16 cols); reduce over 4 lanes
    {
        const int row = tid >> 2, q = tid & 3;
        float s1 = 0.f, s2 = 0.f;
        #pragma unroll
        for (int i = 0; i < 16; ++i) {
            int c = q * 16 + i;
            float v = Cs[row][c];
            s1 = fmaf(v, a1[c0 + c], s1);
            s2 = fmaf(v, a2[c0 + c], s2);
        }
        s1 += __shfl_xor_sync(0xffffffffu, s1, 1);
        s2 += __shfl_xor_sync(0xffffffffu, s2, 1);
        s1 += __shfl_xor_sync(0xffffffffu, s1, 2);
        s2 += __shfl_xor_sync(0xffffffffu, s2, 2);
        if (q == 0 && r0 + row < Nn) {
            const int sh = s * Hh + h;
            g_e1[sh * Nn + r0 + row] = s1;
            g_e2[sh * Nn + r0 + row] = s2;
        }
    }

    // fp16 Wh store (coalesced): 64 rows x 32 half2
    __half2* dst = (__half2*)g_Wh16;
    #pragma unroll
    for (int k = 0; k < 8; ++k) {
        int idx = k * 256 + tid;
        int r = idx >> 5, p = idx & 31;
        if (r0 + r < Nn) {
            dst[((size_t)s * Nn + r0 + r) * (HF / 2) + (c0 >> 1) + p] =
                __floats2half2_rn(Cs[r][2 * p], Cs[r][2 * p + 1]);
        }
    }
}

// ---------------- attention softmax + uint4 gather aggregation (fp16 out) ------------
__global__ void attn_agg() {
    const int n = blockIdx.x, s = blockIdx.y;
    const int t = threadIdx.x;
    const int h = t >> 5, lane = t & 31;
    __shared__ int snbr[MAXD];
    __shared__ float sw[Hh][MAXD];
    __shared__ float sred[4][HF];

    const int cnt = min(g_cnt[n], MAXD);
    for (int j = t; j < cnt; j += 128) snbr[j] = g_nbr[n * MAXD + j];
    __syncthreads();

    // phase 1: softmax over neighbors for head h (warp h)
    const int sh = s * Hh + h;
    const float e1v = g_e1[sh * Nn + n];
    const float* e2r = g_e2 + (size_t)sh * Nn;
    float ev[4];
    float mx = -1e30f;
    #pragma unroll
    for (int k = 0; k < 4; ++k) {
        int j = k * 32 + lane;
        float e = -1e30f;
        if (j < cnt) {
            float tv = e1v + e2r[snbr[j]];
            e = tv > 0.f ? tv : LEAKc * tv;
        }
        ev[k] = e;
        mx = fmaxf(mx, e);
    }
    #pragma unroll
    for (int o = 16; o; o >>= 1) mx = fmaxf(mx, __shfl_xor_sync(0xffffffffu, mx, o));
    float sum = 0.f;
    #pragma unroll
    for (int k = 0; k < 4; ++k) {
        float w = (k * 32 + lane < cnt) ? __expf(ev[k] - mx) : 0.f;
        ev[k] = w;
        sum += w;
    }
    #pragma unroll
    for (int o = 16; o; o >>= 1) sum += __shfl_xor_sync(0xffffffffu, sum, o);
    const float inv = 1.f / sum;
    #pragma unroll
    for (int k = 0; k < 4; ++k) {
        int j = k * 32 + lane;
        if (j < cnt) sw[h][j] = ev[k] * inv;
    }
    __syncthreads();

    // phase 2: thread (g = t>>5, c = t&31); chunk c = 16B = 8 halfs of the 512B row
    const int g = t >> 5, c = t & 31;
    const int hc = c >> 3;                 // head of this chunk
    const size_t rowB = (size_t)s * Nn;
    const uint4* Whv = (const uint4*)g_Wh16;
    float acc[8] = {};
    #pragma unroll 2
    for (int j0 = 0; j0 < cnt; j0 += 4) {
        int j = j0 + g;
        if (j < cnt) {
            int m = snbr[j];
            float w = sw[hc][j];
            uint4 v = Whv[(rowB + m) * 32 + c];
            float2 f0 = __half22float2(*(__half2*)&v.x);
            float2 f1 = __half22float2(*(__half2*)&v.y);
            float2 f2 = __half22float2(*(__half2*)&v.z);
            float2 f3 = __half22float2(*(__half2*)&v.w);
            acc[0] = fmaf(w, f0.x, acc[0]); acc[1] = fmaf(w, f0.y, acc[1]);
            acc[2] = fmaf(w, f1.x, acc[2]); acc[3] = fmaf(w, f1.y, acc[3]);
            acc[4] = fmaf(w, f2.x, acc[4]); acc[5] = fmaf(w, f2.y, acc[5]);
            acc[6] = fmaf(w, f3.x, acc[6]); acc[7] = fmaf(w, f3.y, acc[7]);
        }
    }
    #pragma unroll
    for (int i = 0; i < 8; ++i) sred[g][c * 8 + i] = acc[i];
    __syncthreads();

    // reduce 4 partials, elu, fp16 store (thread t -> hf {2t, 2t+1})
    float vx = sred[0][2 * t]     + sred[1][2 * t]     + sred[2][2 * t]     + sred[3][2 * t];
    float vy = sred[0][2 * t + 1] + sred[1][2 * t + 1] + sred[2][2 * t + 1] + sred[3][2 * t + 1];
    vx = vx > 0.f ? vx : (__expf(vx) - 1.f);
    vy = vy > 0.f ? vy : (__expf(vy) - 1.f);
    ((__half2*)g_hpr16)[(rowB + n) * (HF / 2) + t] = __floats2half2_rn(vx, vy);
}

// ================= fp16 wmma mix GEMM: h_next = a*x + (1-a)*(hpr16 @ WgT16 + bg) =====
// grid (Ss, 8), block 256 (8 warps). A fragments loaded straight from global.
#define MBS_LD 72
__global__ void gemm_mix_tc(const float* __restrict__ bias,
                            const float* __restrict__ resid,
                            float* __restrict__ Cm,
                            __half* __restrict__ Cm16) {
    __shared__ __align__(16) char smemRaw[256 * MBS_LD * 2];   // Bs, reused as Cs
    __half (*Bs)[MBS_LD] = (__half(*)[MBS_LD])smemRaw;
    float (*Cs)[68] = (float(*)[68])smemRaw;                   // 17408 <= 36864

    const int s = blockIdx.x;
    const int r0 = blockIdx.y * 64;
    const int tid = threadIdx.x;
    const int wid = tid >> 5;
    const int wm = wid & 3, wn = wid >> 2;

    // stage B: 256 rows x 64 halfs (8 uint4/row), 8 uint4/thread
    {
        const uint4* src = (const uint4*)g_WgT16;
        #pragma unroll
        for (int k = 0; k < 8; ++k) {
            int idx = k * 256 + tid;
            int r = idx >> 3, p = idx & 7;
            *(uint4*)&Bs[r][p * 8] = src[r * 8 + p];
        }
    }
    __syncthreads();

    const __half* Aslice = g_hpr16 + (size_t)s * Nn * HF;      // padded tail -> safe OOB rows
    wmma::fragment<wmma::accumulator, 16, 16, 16, float> fc[2];
    wmma::fill_fragment(fc[0], 0.f);
    wmma::fill_fragment(fc[1], 0.f);
    #pragma unroll
    for (int k0 = 0; k0 < HF; k0 += 16) {
        wmma::fragment<wmma::matrix_a, 16, 16, 16, __half, wmma::row_major> fa;
        wmma::load_matrix_sync(fa, Aslice + (size_t)(r0 + wm * 16) * HF + k0, HF);
        #pragma unroll
        for (int sub = 0; sub < 2; ++sub) {
            wmma::fragment<wmma::matrix_b, 16, 16, 16, __half, wmma::row_major> fb;
            wmma::load_matrix_sync(fb, &Bs[k0][wn * 32 + sub * 16], MBS_LD);
            wmma::mma_sync(fc[sub], fa, fb, fc[sub]);
        }
    }
    __syncthreads();   // all warps done reading Bs; reuse as Cs
    wmma::store_matrix_sync(&Cs[wm * 16][wn * 32], fc[0], 68, wmma::mem_row_major);
    wmma::store_matrix_sync(&Cs[wm * 16][wn * 32 + 16], fc[1], 68, wmma::mem_row_major);
    __syncthreads();

    #pragma unroll
    for (int k = 0; k < 16; ++k) {
        int idx = k * 256 + tid;
        int r = idx >> 6, c = idx & 63;
        int row = r0 + r;
        if (row < Nn) {
            size_t oidx = ((size_t)s * Nn + row) * Cc + c;
            float v = ALPHAc * resid[oidx] + (1.f - ALPHAc) * (Cs[r][c] + bias[c]);
            Cm[oidx] = v;
            Cm16[oidx] = __float2half_rn(v);
        }
    }
}

// ---------------- final: out[b,o,n,t] = bm[o] + Wm @ [x; h1; h2] (exact fp32) ----------
__global__ void final_out(const float* __restrict__ xT,
                          const float* __restrict__ h1,
                          const float* __restrict__ h2,
                          const float* __restrict__ bm,
                          float* __restrict__ out) {
    __shared__ float sX[16][64], sH1[16][64], sH2[16][64];
    const int s = blockIdx.x;
    const int n0 = blockIdx.y * 16;
    const int tid = threadIdx.x;
    for (int i = tid; i < 16 * 64; i += 256) {
        int nl = i >> 6, c = i & 63;
        int n = n0 + nl;
        size_t idx = ((size_t)s * Nn + (n < Nn ? n : 0)) * Cc + c;
        sX[nl][c]  = (n < Nn) ? xT[idx] : 0.f;
        sH1[nl][c] = (n < Nn) ? h1[idx] : 0.f;
        sH2[nl][c] = (n < Nn) ? h2[idx] : 0.f;
    }
    __syncthreads();
    const int o = tid & 63, ng = tid >> 6;
    float acc[4] = {0.f, 0.f, 0.f, 0.f};
    #pragma unroll 4
    for (int c = 0; c < 64; ++c) {
        float w0 = g_WmT[c * Cc + o];
        float w1 = g_WmT[(64 + c) * Cc + o];
        float w2 = g_WmT[(128 + c) * Cc + o];
        #pragma unroll
        for (int r = 0; r < 4; ++r) {
            int nl = ng + r * 4;
            acc[r] = fmaf(w0, sX[nl][c], fmaf(w1, sH1[nl][c], fmaf(w2, sH2[nl][c], acc[r])));
        }
    }
    const int b = s / Tt, t = s % Tt;
    const float bias = bm[o];
    #pragma unroll
    for (int r = 0; r < 4; ++r) {
        int n = n0 + ng + r * 4;
        if (n < Nn)
            out[(((size_t)b * Cc + o) * Nn + n) * Tt + t] = acc[r] + bias;
    }
}

// ---------------- launch ----------------
extern "C" void kernel_launch(void* const* d_in, const int* in_sizes, int n_in,
                              void* d_out, int out_size) {
    const float* x   = (const float*)d_in[0];
    const float* adj = (const float*)d_in[1];
    const float* W   = (const float*)d_in[2];
    const float* a1  = (const float*)d_in[3];
    const float* a2  = (const float*)d_in[4];
    const float* Wg  = (const float*)d_in[5];
    const float* bg  = (const float*)d_in[6];
    const float* Wm  = (const float*)d_in[7];
    const float* bm  = (const float*)d_in[8];
    float* out = (float*)d_out;

    float *xT, *h1T, *h2T;
    __half *xT16, *h1T16, *h2T16;
    cudaGetSymbolAddress((void**)&xT,    g_xT);
    cudaGetSymbolAddress((void**)&h1T,   g_h1T);
    cudaGetSymbolAddress((void**)&h2T,   g_h2T);
    cudaGetSymbolAddress((void**)&xT16,  g_xT16);
    cudaGetSymbolAddress((void**)&h1T16, g_h1T16);
    cudaGetSymbolAddress((void**)&h2T16, g_h2T16);

    prep_all<<<1213, 256>>>(adj, W, Wg, Wm, x, xT);

    const __half* hin16 = xT16;
    float* hb[2] = {h1T, h2T};
    __half* hb16[2] = {h1T16, h2T16};
    for (int it = 0; it < 2; ++it) {
        gemm_proj16<<<dim3(Ss, 8, Hh), 256>>>(hin16, a1, a2);
        attn_agg<<<dim3(Nn, Ss), 128>>>();
        gemm_mix_tc<<<dim3(Ss, 8), 256>>>(bg, xT, hb[it], hb16[it]);
        hin16 = hb16[it];
    }
    final_out<<<dim3(Ss, (Nn + 15) / 16), 256>>>(xT, h1T, h2T, bm, out);
}

// round 7
// speedup vs baseline: 1.4919x; 1.0212x over previous
#include <cuda_runtime.h>
#include <cuda_fp16.h>
#include <mma.h>
#include <cstdint>

using namespace nvcuda;

// Problem constants
#define Bb 8
#define Cc 64
#define Nn 500
#define Tt 12
#define Hh 4
#define Ff 64
#define Ss (Bb * Tt)   // 96 slices (b,t)
#define HF (Hh * Ff)   // 256
#define MAXD 128
#define ROWPAD 16
#define ALPHAc 0.05f
#define LEAKc 0.2f

// ---------------- scratch (device globals; no allocation) ----------------
__device__ float   g_xT[Ss * Nn * Cc];                   // [s,n,c] fp32 (final path)
__device__ __half  g_xT16[Ss * Nn * Cc];                 // fp16 iterates
__device__ __half  g_h1T16[Ss * Nn * Cc];
__device__ __half  g_h2T16[Ss * Nn * Cc];
__device__ __half  g_Wh16[(size_t)Ss * Nn * HF];         // [s,n,hf] fp16
__device__ __half  g_hpr16[((size_t)Ss * Nn + ROWPAD) * HF]; // padded for OOB frag rows
__device__ float   g_e1[Ss * Hh * Nn];                   // [(s*H+h)*N + n]
__device__ float   g_e2[Ss * Hh * Nn];
__device__ __half  g_Wcat16[Cc * HF];                    // [c, h*F+f] fp16
__device__ __half  g_WgT16[HF * Cc];                     // [hf, o] fp16
__device__ float   g_WmT[3 * Cc * Cc];                   // [c_global, o]
__device__ int     g_cnt[Nn];
__device__ int     g_nbr[Nn * MAXD];

// ================= merged prep: nbr list + weight layouts + input transpose =========
__global__ void prep_all(const float* __restrict__ adj,
                         const float* __restrict__ W,
                         const float* __restrict__ Wg,
                         const float* __restrict__ Wm,
                         const float* __restrict__ x,
                         float* __restrict__ xT) {
    __shared__ float sm[16][193];
    const int blk = blockIdx.x;
    if (blk < 125) {
        if (threadIdx.x >= 128) return;
        int warp = threadIdx.x >> 5;
        int lane = threadIdx.x & 31;
        int n = blk * 4 + warp;
        if (n >= Nn) return;
        int base = 0;
        for (int m0 = 0; m0 < 512; m0 += 32) {
            int m = m0 + lane;
            bool p = (m < Nn) && (adj[n * Nn + m] > 0.f || m == n);
            unsigned mask = __ballot_sync(0xffffffffu, p);
            if (p) {
                int r = __popc(mask & ((1u << lane) - 1));
                if (base + r < MAXD) g_nbr[n * MAXD + base + r] = m;
            }
            base += __popc(mask);
        }
        if (lane == 0) g_cnt[n] = base < MAXD ? base : MAXD;
    } else if (blk < 189) {
        int i = (blk - 125) * 256 + threadIdx.x;
        if (i < Hh * Cc * Ff) {  // Wcat16[c, h*F+f] = W[h,c,f]
            int f = i % Ff; int rest = i / Ff;
            int c = rest % Cc; int h = rest / Cc;
            g_Wcat16[c * HF + h * Ff + f] = __float2half_rn(W[(h * Cc + c) * Ff + f]);
        }
        if (i < HF * Cc) {       // WgT16[hf, o] = half(Wg[o, hf])
            int o = i % Cc; int hf = i / Cc;
            g_WgT16[hf * Cc + o] = __float2half_rn(Wg[o * HF + hf]);
        }
        if (i < 3 * Cc * Cc) {   // WmT[c, o] = Wm[o, c]
            int o = i % Cc; int c = i / Cc;
            g_WmT[c * Cc + o] = Wm[o * (3 * Cc) + c];
        }
    } else {
        // transpose: x[b,c,n,t] -> xT[s,n,c] (fp32 + fp16)
        if (threadIdx.x >= 192) return;
        const int bi = blk - 189;
        const int nb = bi & 31, cb = (bi >> 5) & 3, b = bi >> 7;
        const int c0 = cb * 16, n0 = nb * 16;
        const int tt_ = threadIdx.x;
        const int ni_l = tt_ / 12, tl = tt_ % 12;
        const int n_l = n0 + ni_l;
        #pragma unroll
        for (int ci = 0; ci < 16; ++ci) {
            float v = 0.f;
            if (n_l < Nn)
                v = x[(((size_t)b * Cc + c0 + ci) * Nn + n_l) * Tt + tl];
            sm[ci][tt_] = v;
        }
        __syncthreads();
        #pragma unroll
        for (int rep = 0; rep < 16; ++rep) {
            int idx = rep * 192 + tt_;
            int ci = idx & 15;
            int rest = idx >> 4;
            int ni = rest / 12, t = rest % 12;
            int n = n0 + ni;
            if (n < Nn) {
                size_t oi = (((size_t)(b * Tt + t) * Nn) + n) * Cc + c0 + ci;
                float v = sm[ci][rest];
                xT[oi] = v;
                g_xT16[oi] = __float2half_rn(v);
            }
        }
    }
}

// ================= fp16 HMMA projection GEMM (2 heads/block) + e1/e2 + Wh ===========
// grid (Ss, 8, 2), block 256 (8 warps). Tile 64 rows x 128 cols (heads 2z, 2z+1), K=64.
#define PAS_LD 72
#define PBS_LD 136
#define PCS_LD 132
__global__ void gemm_proj16(const __half* __restrict__ Ain,
                            const float* __restrict__ a1,
                            const float* __restrict__ a2) {
    __shared__ __align__(16) char smemRaw[64 * PCS_LD * 4];      // 33792 B
    __half (*As)[PAS_LD] = (__half(*)[PAS_LD])smemRaw;           // 9216 B
    __half (*Bs)[PBS_LD] = (__half(*)[PBS_LD])(smemRaw + 64 * PAS_LD * 2); // 17408 B
    float (*Cs)[PCS_LD] = (float(*)[PCS_LD])smemRaw;             // reuse after MMA

    const int s = blockIdx.x;
    const int r0 = blockIdx.y * 64;
    const int z = blockIdx.z;            // head pair
    const int c0 = z * 128;
    const int tid = threadIdx.x;
    const int wid = tid >> 5;
    const int wm = wid & 3, wn = wid >> 2;   // rows wm*16, cols wn*64

    // stage A: 64 rows x 64 halfs (8 uint4/row), 2 uint4/thread
    {
        const uint4* srcA = (const uint4*)(Ain + (size_t)s * Nn * Cc);
        #pragma unroll
        for (int k = 0; k < 2; ++k) {
            int idx = k * 256 + tid;
            int r = idx >> 3, p = idx & 7;
            int row = r0 + r;
            uint4 v = make_uint4(0, 0, 0, 0);
            if (row < Nn) v = srcA[(size_t)row * 8 + p];
            *(uint4*)&As[r][p * 8] = v;
        }
    }
    // stage B: Wcat16 rows 0..63, cols c0..c0+127 (16 uint4/row), 4 uint4/thread
    {
        const uint4* srcB = (const uint4*)(g_Wcat16 + c0);
        #pragma unroll
        for (int k = 0; k < 4; ++k) {
            int idx = k * 256 + tid;
            int r = idx >> 4, p = idx & 15;
            *(uint4*)&Bs[r][p * 8] = srcB[r * 32 + p];   // row stride 256 half = 32 uint4
        }
    }
    __syncthreads();

    wmma::fragment<wmma::accumulator, 16, 16, 16, float> fc[4];
    #pragma unroll
    for (int j = 0; j < 4; ++j) wmma::fill_fragment(fc[j], 0.f);
    #pragma unroll
    for (int k0 = 0; k0 < 64; k0 += 16) {
        wmma::fragment<wmma::matrix_a, 16, 16, 16, __half, wmma::row_major> fa;
        wmma::load_matrix_sync(fa, &As[wm * 16][k0], PAS_LD);
        #pragma unroll
        for (int j = 0; j < 4; ++j) {
            wmma::fragment<wmma::matrix_b, 16, 16, 16, __half, wmma::row_major> fb;
            wmma::load_matrix_sync(fb, &Bs[k0][wn * 64 + j * 16], PBS_LD);
            wmma::mma_sync(fc[j], fa, fb, fc[j]);
        }
    }
    __syncthreads();   // done reading As/Bs; reuse as Cs
    #pragma unroll
    for (int j = 0; j < 4; ++j)
        wmma::store_matrix_sync(&Cs[wm * 16][wn * 64 + j * 16], fc[j], PCS_LD,
                                wmma::mem_row_major);
    __syncthreads();

    // fused e1/e2 for both heads: thread -> row tid>>2, quarter q = tid&3 (16 cols/head)
    {
        const int row = tid >> 2, q = tid & 3;
        #pragma unroll
        for (int hh = 0; hh < 2; ++hh) {
            const int hg = z * 2 + hh;           // global head
            float s1 = 0.f, s2 = 0.f;
            #pragma unroll
            for (int i = 0; i < 16; ++i) {
                int cl = hh * 64 + q * 16 + i;
                float v = Cs[row][cl];
                s1 = fmaf(v, a1[hg * Ff + q * 16 + i], s1);
                s2 = fmaf(v, a2[hg * Ff + q * 16 + i], s2);
            }
            s1 += __shfl_xor_sync(0xffffffffu, s1, 1);
            s2 += __shfl_xor_sync(0xffffffffu, s2, 1);
            s1 += __shfl_xor_sync(0xffffffffu, s1, 2);
            s2 += __shfl_xor_sync(0xffffffffu, s2, 2);
            if (q == 0 && r0 + row < Nn) {
                const int sh = s * Hh + hg;
                g_e1[sh * Nn + r0 + row] = s1;
                g_e2[sh * Nn + r0 + row] = s2;
            }
        }
    }

    // fp16 Wh store (coalesced): 64 rows x 64 half2
    __half2* dst = (__half2*)g_Wh16;
    #pragma unroll
    for (int k = 0; k < 16; ++k) {
        int idx = k * 256 + tid;
        int r = idx >> 6, p = idx & 63;
        if (r0 + r < Nn) {
            dst[((size_t)s * Nn + r0 + r) * (HF / 2) + z * 64 + p] =
                __floats2half2_rn(Cs[r][2 * p], Cs[r][2 * p + 1]);
        }
    }
}

// ---------------- attention softmax + uint4 gather aggregation (fp16 out) ------------
__global__ void attn_agg() {
    const int n = blockIdx.x, s = blockIdx.y;
    const int t = threadIdx.x;
    const int h = t >> 5, lane = t & 31;
    __shared__ int snbr[MAXD];
    __shared__ float sw[Hh][MAXD];
    __shared__ float sred[4][HF];

    const int cnt = min(g_cnt[n], MAXD);
    for (int j = t; j < cnt; j += 128) snbr[j] = g_nbr[n * MAXD + j];
    __syncthreads();

    // phase 1: softmax over neighbors for head h (warp h)
    const int sh = s * Hh + h;
    const float e1v = g_e1[sh * Nn + n];
    const float* e2r = g_e2 + (size_t)sh * Nn;
    float ev[4];
    float mx = -1e30f;
    #pragma unroll
    for (int k = 0; k < 4; ++k) {
        int j = k * 32 + lane;
        float e = -1e30f;
        if (j < cnt) {
            float tv = e1v + e2r[snbr[j]];
            e = tv > 0.f ? tv : LEAKc * tv;
        }
        ev[k] = e;
        mx = fmaxf(mx, e);
    }
    #pragma unroll
    for (int o = 16; o; o >>= 1) mx = fmaxf(mx, __shfl_xor_sync(0xffffffffu, mx, o));
    float sum = 0.f;
    #pragma unroll
    for (int k = 0; k < 4; ++k) {
        float w = (k * 32 + lane < cnt) ? __expf(ev[k] - mx) : 0.f;
        ev[k] = w;
        sum += w;
    }
    #pragma unroll
    for (int o = 16; o; o >>= 1) sum += __shfl_xor_sync(0xffffffffu, sum, o);
    const float inv = 1.f / sum;
    #pragma unroll
    for (int k = 0; k < 4; ++k) {
        int j = k * 32 + lane;
        if (j < cnt) sw[h][j] = ev[k] * inv;
    }
    __syncthreads();

    // phase 2: thread (g = t>>5, c = t&31); chunk c = 16B = 8 halfs of the 512B row
    const int g = t >> 5, c = t & 31;
    const int hc = c >> 3;                 // head of this chunk
    const size_t rowB = (size_t)s * Nn;
    const uint4* Whv = (const uint4*)g_Wh16;
    float acc[8] = {};
    #pragma unroll 2
    for (int j0 = 0; j0 < cnt; j0 += 4) {
        int j = j0 + g;
        if (j < cnt) {
            int m = snbr[j];
            float w = sw[hc][j];
            uint4 v = Whv[(rowB + m) * 32 + c];
            float2 f0 = __half22float2(*(__half2*)&v.x);
            float2 f1 = __half22float2(*(__half2*)&v.y);
            float2 f2 = __half22float2(*(__half2*)&v.z);
            float2 f3 = __half22float2(*(__half2*)&v.w);
            acc[0] = fmaf(w, f0.x, acc[0]); acc[1] = fmaf(w, f0.y, acc[1]);
            acc[2] = fmaf(w, f1.x, acc[2]); acc[3] = fmaf(w, f1.y, acc[3]);
            acc[4] = fmaf(w, f2.x, acc[4]); acc[5] = fmaf(w, f2.y, acc[5]);
            acc[6] = fmaf(w, f3.x, acc[6]); acc[7] = fmaf(w, f3.y, acc[7]);
        }
    }
    #pragma unroll
    for (int i = 0; i < 8; ++i) sred[g][c * 8 + i] = acc[i];
    __syncthreads();

    // reduce 4 partials, elu, fp16 store (thread t -> hf {2t, 2t+1})
    float vx = sred[0][2 * t]     + sred[1][2 * t]     + sred[2][2 * t]     + sred[3][2 * t];
    float vy = sred[0][2 * t + 1] + sred[1][2 * t + 1] + sred[2][2 * t + 1] + sred[3][2 * t + 1];
    vx = vx > 0.f ? vx : (__expf(vx) - 1.f);
    vy = vy > 0.f ? vy : (__expf(vy) - 1.f);
    ((__half2*)g_hpr16)[(rowB + n) * (HF / 2) + t] = __floats2half2_rn(vx, vy);
}

// ================= fp16 wmma mix GEMM: h_next16 = a*x16 + (1-a)*(hpr16 @ WgT16 + bg) ==
// grid (Ss, 8), block 256 (8 warps). A fragments loaded straight from global.
#define MBS_LD 72
__global__ void gemm_mix_tc(const float* __restrict__ bias,
                            const __half* __restrict__ resid16,
                            __half* __restrict__ Cm16) {
    __shared__ __align__(16) char smemRaw[256 * MBS_LD * 2];   // Bs, reused as Cs
    __half (*Bs)[MBS_LD] = (__half(*)[MBS_LD])smemRaw;
    float (*Cs)[68] = (float(*)[68])smemRaw;                   // 17408 <= 36864

    const int s = blockIdx.x;
    const int r0 = blockIdx.y * 64;
    const int tid = threadIdx.x;
    const int wid = tid >> 5;
    const int wm = wid & 3, wn = wid >> 2;

    // stage B: 256 rows x 64 halfs (8 uint4/row), 8 uint4/thread
    {
        const uint4* src = (const uint4*)g_WgT16;
        #pragma unroll
        for (int k = 0; k < 8; ++k) {
            int idx = k * 256 + tid;
            int r = idx >> 3, p = idx & 7;
            *(uint4*)&Bs[r][p * 8] = src[r * 8 + p];
        }
    }
    __syncthreads();

    const __half* Aslice = g_hpr16 + (size_t)s * Nn * HF;      // padded tail -> safe OOB rows
    wmma::fragment<wmma::accumulator, 16, 16, 16, float> fc[2];
    wmma::fill_fragment(fc[0], 0.f);
    wmma::fill_fragment(fc[1], 0.f);
    #pragma unroll
    for (int k0 = 0; k0 < HF; k0 += 16) {
        wmma::fragment<wmma::matrix_a, 16, 16, 16, __half, wmma::row_major> fa;
        wmma::load_matrix_sync(fa, Aslice + (size_t)(r0 + wm * 16) * HF + k0, HF);
        #pragma unroll
        for (int sub = 0; sub < 2; ++sub) {
            wmma::fragment<wmma::matrix_b, 16, 16, 16, __half, wmma::row_major> fb;
            wmma::load_matrix_sync(fb, &Bs[k0][wn * 32 + sub * 16], MBS_LD);
            wmma::mma_sync(fc[sub], fa, fb, fc[sub]);
        }
    }
    __syncthreads();   // all warps done reading Bs; reuse as Cs
    wmma::store_matrix_sync(&Cs[wm * 16][wn * 32], fc[0], 68, wmma::mem_row_major);
    wmma::store_matrix_sync(&Cs[wm * 16][wn * 32 + 16], fc[1], 68, wmma::mem_row_major);
    __syncthreads();

    #pragma unroll
    for (int k = 0; k < 16; ++k) {
        int idx = k * 256 + tid;
        int r = idx >> 6, c = idx & 63;
        int row = r0 + r;
        if (row < Nn) {
            size_t oidx = ((size_t)s * Nn + row) * Cc + c;
            float v = ALPHAc * __half2float(resid16[oidx])
                    + (1.f - ALPHAc) * (Cs[r][c] + bias[c]);
            Cm16[oidx] = __float2half_rn(v);
        }
    }
}

// ---------------- final: out[b,o,n,t] = bm[o] + Wm @ [x; h1; h2] ----------------
__global__ void final_out(const float* __restrict__ xT,
                          const __half* __restrict__ h1,
                          const __half* __restrict__ h2,
                          const float* __restrict__ bm,
                          float* __restrict__ out) {
    __shared__ float sX[16][64], sH1[16][64], sH2[16][64];
    const int s = blockIdx.x;
    const int n0 = blockIdx.y * 16;
    const int tid = threadIdx.x;
    for (int i = tid; i < 16 * 64; i += 256) {
        int nl = i >> 6, c = i & 63;
        int n = n0 + nl;
        size_t idx = ((size_t)s * Nn + (n < Nn ? n : 0)) * Cc + c;
        sX[nl][c]  = (n < Nn) ? xT[idx] : 0.f;
        sH1[nl][c] = (n < Nn) ? __half2float(h1[idx]) : 0.f;
        sH2[nl][c] = (n < Nn) ? __half2float(h2[idx]) : 0.f;
    }
    __syncthreads();
    const int o = tid & 63, ng = tid >> 6;
    float acc[4] = {0.f, 0.f, 0.f, 0.f};
    #pragma unroll 4
    for (int c = 0; c < 64; ++c) {
        float w0 = g_WmT[c * Cc + o];
        float w1 = g_WmT[(64 + c) * Cc + o];
        float w2 = g_WmT[(128 + c) * Cc + o];
        #pragma unroll
        for (int r = 0; r < 4; ++r) {
            int nl = ng + r * 4;
            acc[r] = fmaf(w0, sX[nl][c], fmaf(w1, sH1[nl][c], fmaf(w2, sH2[nl][c], acc[r])));
        }
    }
    const int b = s / Tt, t = s % Tt;
    const float bias = bm[o];
    #pragma unroll
    for (int r = 0; r < 4; ++r) {
        int n = n0 + ng + r * 4;
        if (n < Nn)
            out[(((size_t)b * Cc + o) * Nn + n) * Tt + t] = acc[r] + bias;
    }
}

// ---------------- launch ----------------
extern "C" void kernel_launch(void* const* d_in, const int* in_sizes, int n_in,
                              void* d_out, int out_size) {
    const float* x   = (const float*)d_in[0];
    const float* adj = (const float*)d_in[1];
    const float* W   = (const float*)d_in[2];
    const float* a1  = (const float*)d_in[3];
    const float* a2  = (const float*)d_in[4];
    const float* Wg  = (const float*)d_in[5];
    const float* bg  = (const float*)d_in[6];
    const float* Wm  = (const float*)d_in[7];
    const float* bm  = (const float*)d_in[8];
    float* out = (float*)d_out;

    float* xT;
    __half *xT16, *h1T16, *h2T16;
    cudaGetSymbolAddress((void**)&xT,    g_xT);
    cudaGetSymbolAddress((void**)&xT16,  g_xT16);
    cudaGetSymbolAddress((void**)&h1T16, g_h1T16);
    cudaGetSymbolAddress((void**)&h2T16, g_h2T16);

    prep_all<<<1213, 256>>>(adj, W, Wg, Wm, x, xT);

    const __half* hin16 = xT16;
    __half* hb16[2] = {h1T16, h2T16};
    for (int it = 0; it < 2; ++it) {
        gemm_proj16<<<dim3(Ss, 8, 2), 256>>>(hin16, a1, a2);
        attn_agg<<<dim3(Nn, Ss), 128>>>();
        gemm_mix_tc<<<dim3(Ss, 8), 256>>>(bg, xT16, hb16[it]);
        hin16 = hb16[it];
    }
    final_out<<<dim3(Ss, (Nn + 15) / 16), 256>>>(xT, h1T16, h2T16, bm, out);
}